// round 6
// baseline (speedup 1.0000x reference)
#include <cuda_runtime.h>
#include <cstdint>

// ---------------------------------------------------------------------------
// RNN-T joint network (sm_103 legacy tensor path):
//   XT = x@W_tr + b_tr            [1600, 256]
//   YP = y@W_pr + b_pr            [400, 256]
//   Z  = tf32(tanh(XT[bt] + YP[b,u]))   [160000, 256]
//   out= Z @ W_cls + b_cls        [160000, 1024]
// Joint GEMM: mma.sync tf32, CTA 128x128, 4 warps of 64x64 (2Mx2N),
// ldmatrix.x4 feeds, stride-36 + XOR-chunk swizzle (conflict-free loads AND
// stores), 3-stage cp.async, 2 CTAs/SM.
// ---------------------------------------------------------------------------

#define B_  4
#define T_  400
#define U_  100
#define DTR 768
#define DPR 640
#define DJ  256
#define V_  1024
#define M_TOTAL (B_ * T_ * U_)   // 160000

__device__ float g_XT[(size_t)B_ * T_ * DJ];
__device__ float g_YP[(size_t)B_ * U_ * DJ];
__device__ float g_Z[(size_t)M_TOTAL * DJ];   // 164 MB, tf32-rounded
__device__ float g_Wt[(size_t)V_ * DJ];       // tf32(W_cls^T), n-major [V][DJ]

__device__ __forceinline__ float to_tf32(float f) {
    uint32_t u;
    asm("cvt.rna.tf32.f32 %0, %1;" : "=r"(u) : "f"(f));
    return __uint_as_float(u);
}

__device__ __forceinline__ float fast_tanh(float x) {
    float r;
    asm("tanh.approx.f32 %0, %1;" : "=f"(r) : "f"(x));
    return r;
}

__device__ __forceinline__ void mma_tf32(float* c, const uint32_t* a, const uint32_t* b) {
    asm volatile(
        "mma.sync.aligned.m16n8k8.row.col.f32.tf32.tf32.f32 "
        "{%0,%1,%2,%3}, {%4,%5,%6,%7}, {%8,%9}, {%0,%1,%2,%3};\n"
        : "+f"(c[0]), "+f"(c[1]), "+f"(c[2]), "+f"(c[3])
        : "r"(a[0]), "r"(a[1]), "r"(a[2]), "r"(a[3]), "r"(b[0]), "r"(b[1]));
}

__device__ __forceinline__ void ldsm_x4(uint32_t& r0, uint32_t& r1, uint32_t& r2,
                                        uint32_t& r3, uint32_t addr) {
    asm volatile("ldmatrix.sync.aligned.m8n8.x4.shared.b16 {%0,%1,%2,%3}, [%4];"
                 : "=r"(r0), "=r"(r1), "=r"(r2), "=r"(r3) : "r"(addr));
}

__device__ __forceinline__ uint32_t smem_u32(const void* p) {
    uint32_t a;
    asm("{ .reg .u64 t; cvta.to.shared.u64 t, %1; cvt.u32.u64 %0, t; }" : "=r"(a) : "l"(p));
    return a;
}

// ---------------------------------------------------------------------------
// Stage 0: Wt[n][k] = tf32(W_cls[k][n])
// ---------------------------------------------------------------------------
__global__ __launch_bounds__(256)
void transpose_w(const float* __restrict__ W, float* __restrict__ Wt) {
    __shared__ float t[32][33];
    int n0 = blockIdx.x * 32, k0 = blockIdx.y * 32;
    int tx = threadIdx.x, ty = threadIdx.y;   // (32, 8)
#pragma unroll
    for (int i = 0; i < 32; i += 8)
        t[ty + i][tx] = to_tf32(W[(size_t)(k0 + ty + i) * V_ + n0 + tx]);
    __syncthreads();
#pragma unroll
    for (int i = 0; i < 32; i += 8)
        Wt[(size_t)(n0 + ty + i) * DJ + k0 + tx] = t[tx][ty + i];
}

// ---------------------------------------------------------------------------
// Stage 1: small fp32 GEMM with bias, C[M,256] = A[M,K] @ W[K,256] + bias
// ---------------------------------------------------------------------------
__global__ __launch_bounds__(256)
void gemm_bias_f32(const float* __restrict__ A, const float* __restrict__ W,
                   const float* __restrict__ bias, float* __restrict__ C,
                   int M, int K) {
    const int N = DJ;
    __shared__ float As[16][68];
    __shared__ float Ws[16][68];

    int m0 = blockIdx.x * 64, n0 = blockIdx.y * 64;
    int tid = threadIdx.x;
    int ty = tid >> 4, tx = tid & 15;

    float acc[4][4];
#pragma unroll
    for (int i = 0; i < 4; i++)
#pragma unroll
        for (int j = 0; j < 4; j++) acc[i][j] = 0.f;

    for (int k0 = 0; k0 < K; k0 += 16) {
        {
            int row = tid >> 2, kc = (tid & 3) << 2;
            float4 v = make_float4(0.f, 0.f, 0.f, 0.f);
            int m = m0 + row;
            if (m < M) v = *(const float4*)(A + (size_t)m * K + k0 + kc);
            As[kc + 0][row] = v.x;
            As[kc + 1][row] = v.y;
            As[kc + 2][row] = v.z;
            As[kc + 3][row] = v.w;
        }
        {
            int kr = tid >> 4, nc = (tid & 15) << 2;
            float4 w = *(const float4*)(W + (size_t)(k0 + kr) * N + n0 + nc);
            *(float4*)&Ws[kr][nc] = w;
        }
        __syncthreads();
#pragma unroll
        for (int kk = 0; kk < 16; kk++) {
            float a[4], b[4];
#pragma unroll
            for (int i = 0; i < 4; i++) a[i] = As[kk][ty * 4 + i];
#pragma unroll
            for (int j = 0; j < 4; j++) b[j] = Ws[kk][tx * 4 + j];
#pragma unroll
            for (int i = 0; i < 4; i++)
#pragma unroll
                for (int j = 0; j < 4; j++) acc[i][j] = fmaf(a[i], b[j], acc[i][j]);
        }
        __syncthreads();
    }
#pragma unroll
    for (int i = 0; i < 4; i++) {
        int m = m0 + ty * 4 + i;
        if (m >= M) continue;
#pragma unroll
        for (int j = 0; j < 4; j++) {
            int n = n0 + tx * 4 + j;
            C[(size_t)m * N + n] = acc[i][j] + bias[n];
        }
    }
}

// ---------------------------------------------------------------------------
// Stage 2: Z = tf32_round(tanh_hw(XT[bt,:] + YP[b*U+u,:]))
// ---------------------------------------------------------------------------
__global__ __launch_bounds__(256)
void z_tanh_kernel(const float* __restrict__ XT, const float* __restrict__ YP,
                   float* __restrict__ Z) {
    int i = blockIdx.x * blockDim.x + threadIdx.x;
    const int total4 = M_TOTAL * (DJ / 4);
    if (i >= total4) return;
    int m = i >> 6;
    int q = i & 63;
    int bt = m / U_;
    int u = m - bt * U_;
    int b = bt / T_;

    float4 xv = *(const float4*)(XT + (size_t)bt * DJ + q * 4);
    float4 yv = *(const float4*)(YP + (size_t)(b * U_ + u) * DJ + q * 4);
    float4 z;
    z.x = to_tf32(fast_tanh(xv.x + yv.x));
    z.y = to_tf32(fast_tanh(xv.y + yv.y));
    z.z = to_tf32(fast_tanh(xv.z + yv.z));
    z.w = to_tf32(fast_tanh(xv.w + yv.w));
    *(float4*)(Z + (size_t)m * DJ + q * 4) = z;
}

// ---------------------------------------------------------------------------
// Stage 3: out = Z @ W_cls + b_cls  via mma.sync tf32.
// CTA 128M x 128N, 128 threads, 4 warps of 64x64 (2M x 2N).
// Tiles [128][36] with 16B-chunk XOR swizzle: byte addr = row*144 +
// ((chunk ^ (row&7))<<4).  Loads (ldmatrix) and stores (cp.async) both
// conflict-free.  BK=32, 3-stage cp.async pipeline, 1 sync/chunk, 2 CTAs/SM.
// ---------------------------------------------------------------------------
#define BM 128
#define BN 128
#define BK 32
#define TSTRIDE 36
#define ROWB (TSTRIDE * 4)                            // 144
#define A_STAGE_BYTES (BM * ROWB)                     // 18432
#define B_STAGE_BYTES (BN * ROWB)                     // 18432
#define STAGE_BYTES (A_STAGE_BYTES + B_STAGE_BYTES)   // 36864
#define NSTAGES 3
#define JSMEM (NSTAGES * STAGE_BYTES)                 // 110592

__global__ __launch_bounds__(128, 2)
void joint_gemm_tf32(const float* __restrict__ Z, const float* __restrict__ Wt,
                     const float* __restrict__ bias, float* __restrict__ out) {
    extern __shared__ char sm[];
    const uint32_t smbase = smem_u32(sm);

    const int K = DJ;     // 256
    const int N = V_;     // 1024

    const int n0 = blockIdx.x * BN;
    const int m0 = blockIdx.y * BM;
    const int tid = threadIdx.x;
    const int lane = tid & 31, w = tid >> 5;
    const int warpM = w & 1, warpN = w >> 1;      // 2 x 2
    const int wm0 = warpM * 64, wn0 = warpN * 64;
    const int gid = lane >> 2, tig = lane & 3;

    // ldmatrix per-lane bases. Swizzle XOR value is l8 for all fragment rows
    // (row = base + l8 with 8|base, so row&7 == l8).
    const int l8 = lane & 7, j = lane >> 3;
    const uint32_t aRow = (uint32_t)(wm0 + ((j & 1) << 3) + l8) * ROWB;         // + fm*16*ROWB
    const uint32_t bRow = (uint32_t)A_STAGE_BYTES +
                          (uint32_t)(wn0 + ((j >> 1) << 3) + l8) * ROWB;        // + p*16*ROWB
    const uint32_t cA = (uint32_t)(j >> 1);   // A logical chunk low bit
    const uint32_t cB = (uint32_t)(j & 1);    // B logical chunk low bit
    const uint32_t xorv = (uint32_t)l8;

    // cp.async: warp covers 4 rows x 8 chunks (coalesced 128B per row).
    const int lrow = tid >> 3;     // 0..15, + 16p
    const int lchunk = tid & 7;    // 16B chunk within row

#define LOAD_TILE(c, s) do { \
    uint32_t _sb = smbase + (uint32_t)(s) * STAGE_BYTES; \
    _Pragma("unroll") \
    for (int p = 0; p < 8; p++) { \
        int _r = lrow + p * 16; \
        uint32_t _d = _sb + (uint32_t)_r * ROWB + \
                      ((uint32_t)(lchunk ^ (_r & 7)) << 4); \
        const float* _a = Z + (size_t)(m0 + _r) * K + (c) * BK + lchunk * 4; \
        const float* _b = Wt + (size_t)(n0 + _r) * K + (c) * BK + lchunk * 4; \
        asm volatile("cp.async.cg.shared.global [%0], [%1], 16;" \
                     :: "r"(_d), "l"(_a)); \
        asm volatile("cp.async.cg.shared.global [%0], [%1], 16;" \
                     :: "r"(_d + (uint32_t)A_STAGE_BYTES), "l"(_b)); \
    } \
    asm volatile("cp.async.commit_group;" ::: "memory"); \
} while (0)

    float acc[4][8][4];
#pragma unroll
    for (int fm = 0; fm < 4; fm++)
#pragma unroll
        for (int fn = 0; fn < 8; fn++)
#pragma unroll
            for (int r = 0; r < 4; r++) acc[fm][fn][r] = 0.f;

    LOAD_TILE(0, 0);
    LOAD_TILE(1, 1);

#pragma unroll 1
    for (int c = 0; c < 8; c++) {
        if (c < 7) asm volatile("cp.async.wait_group 1;" ::: "memory");
        else       asm volatile("cp.async.wait_group 0;" ::: "memory");
        __syncthreads();
        if (c + 2 < 8) LOAD_TILE(c + 2, (c + 2) % NSTAGES);

        const uint32_t stg = smbase + (uint32_t)(c % NSTAGES) * STAGE_BYTES;
        const uint32_t aB = stg + aRow;
        const uint32_t bB = stg + bRow;
#pragma unroll
        for (int kk = 0; kk < BK; kk += 8) {
            const uint32_t kc = (uint32_t)(kk >> 2);   // chunk high bits (even)
            uint32_t a[4][4], b[8][2];
            const uint32_t aCh = ((kc | cA) ^ xorv) << 4;
            const uint32_t bCh = ((kc | cB) ^ xorv) << 4;
#pragma unroll
            for (int fm = 0; fm < 4; fm++)
                ldsm_x4(a[fm][0], a[fm][1], a[fm][2], a[fm][3],
                        aB + (uint32_t)fm * (16 * ROWB) + aCh);
#pragma unroll
            for (int p = 0; p < 4; p++)
                ldsm_x4(b[2 * p][0], b[2 * p][1], b[2 * p + 1][0], b[2 * p + 1][1],
                        bB + (uint32_t)p * (16 * ROWB) + bCh);
#pragma unroll
            for (int fm = 0; fm < 4; fm++)
#pragma unroll
                for (int fn = 0; fn < 8; fn++) mma_tf32(acc[fm][fn], a[fm], b[fn]);
        }
    }
#undef LOAD_TILE

    // epilogue: bias + store
#pragma unroll
    for (int fm = 0; fm < 4; fm++) {
        int r0 = m0 + wm0 + fm * 16 + gid;
#pragma unroll
        for (int fn = 0; fn < 8; fn++) {
            int cidx = n0 + wn0 + fn * 8 + 2 * tig;
            float bv0 = __ldg(bias + cidx);
            float bv1 = __ldg(bias + cidx + 1);
            float2 v0 = make_float2(acc[fm][fn][0] + bv0, acc[fm][fn][1] + bv1);
            float2 v1 = make_float2(acc[fm][fn][2] + bv0, acc[fm][fn][3] + bv1);
            *(float2*)(out + (size_t)r0 * N + cidx) = v0;
            *(float2*)(out + (size_t)(r0 + 8) * N + cidx) = v1;
        }
    }
}

// ---------------------------------------------------------------------------
extern "C" void kernel_launch(void* const* d_in, const int* in_sizes, int n_in,
                              void* d_out, int out_size) {
    const float* x     = (const float*)d_in[0];
    const float* y     = (const float*)d_in[1];
    const float* W_tr  = (const float*)d_in[2];
    const float* b_tr  = (const float*)d_in[3];
    const float* W_pr  = (const float*)d_in[4];
    const float* b_pr  = (const float*)d_in[5];
    const float* W_cls = (const float*)d_in[6];
    const float* b_cls = (const float*)d_in[7];
    float* out = (float*)d_out;

    void *pXT, *pYP, *pZ, *pWt;
    cudaGetSymbolAddress(&pXT, g_XT);
    cudaGetSymbolAddress(&pYP, g_YP);
    cudaGetSymbolAddress(&pZ, g_Z);
    cudaGetSymbolAddress(&pWt, g_Wt);

    // Wt = tf32(W_cls^T)
    {
        dim3 grid(V_ / 32, DJ / 32);
        transpose_w<<<grid, dim3(32, 8)>>>(W_cls, (float*)pWt);
    }
    // XT = x @ W_tr + b_tr
    {
        dim3 grid((B_ * T_ + 63) / 64, DJ / 64);
        gemm_bias_f32<<<grid, 256>>>(x, W_tr, b_tr, (float*)pXT, B_ * T_, DTR);
    }
    // YP = y @ W_pr + b_pr
    {
        dim3 grid((B_ * U_ + 63) / 64, DJ / 64);
        gemm_bias_f32<<<grid, 256>>>(y, W_pr, b_pr, (float*)pYP, B_ * U_, DPR);
    }
    // Z = tf32(tanh(XT + YP))
    {
        int total4 = M_TOTAL * (DJ / 4);
        z_tanh_kernel<<<(total4 + 255) / 256, 256>>>((const float*)pXT,
                                                     (const float*)pYP, (float*)pZ);
    }
    // out = Z @ W_cls + b_cls
    {
        cudaFuncSetAttribute(joint_gemm_tf32, cudaFuncAttributeMaxDynamicSharedMemorySize,
                             JSMEM);
        dim3 grid(V_ / BN, M_TOTAL / BM);   // (8, 1250), N fastest for Z reuse
        joint_gemm_tf32<<<grid, 128, JSMEM>>>((const float*)pZ, (const float*)pWt,
                                              b_cls, out);
    }
}

// round 7
// speedup vs baseline: 2.2319x; 2.2319x over previous
#include <cuda_runtime.h>
#include <cuda_fp16.h>
#include <cstdint>

// ---------------------------------------------------------------------------
// RNN-T joint network (sm_103 legacy tensor path, fp16 mma):
//   XT = x@W_tr + b_tr            [1600, 256]  fp32
//   YP = y@W_pr + b_pr            [400, 256]   fp32
//   Zh = fp16(tanh(XT[bt] + YP[b,u]))  [160000, 256]
//   out= Zh @ Wh + b_cls          [160000, 1024]  mma.sync m16n8k16 f16,f32acc
// fp16 has an 11-bit significand == tf32 precision; rel_err unchanged.
// ---------------------------------------------------------------------------

#define B_  4
#define T_  400
#define U_  100
#define DTR 768
#define DPR 640
#define DJ  256
#define V_  1024
#define M_TOTAL (B_ * T_ * U_)   // 160000

__device__ float  g_XT[(size_t)B_ * T_ * DJ];
__device__ float  g_YP[(size_t)B_ * U_ * DJ];
__device__ __half g_Zh[(size_t)M_TOTAL * DJ];   // 82 MB
__device__ __half g_Wh[(size_t)V_ * DJ];        // fp16(W_cls^T), n-major [V][DJ]

__device__ __forceinline__ float fast_tanh(float x) {
    float r;
    asm("tanh.approx.f32 %0, %1;" : "=f"(r) : "f"(x));
    return r;
}

__device__ __forceinline__ void mma_f16(float* c, const uint32_t* a, const uint32_t* b) {
    asm volatile(
        "mma.sync.aligned.m16n8k16.row.col.f32.f16.f16.f32 "
        "{%0,%1,%2,%3}, {%4,%5,%6,%7}, {%8,%9}, {%0,%1,%2,%3};\n"
        : "+f"(c[0]), "+f"(c[1]), "+f"(c[2]), "+f"(c[3])
        : "r"(a[0]), "r"(a[1]), "r"(a[2]), "r"(a[3]), "r"(b[0]), "r"(b[1]));
}

__device__ __forceinline__ void ldsm_x4(uint32_t& r0, uint32_t& r1, uint32_t& r2,
                                        uint32_t& r3, uint32_t addr) {
    asm volatile("ldmatrix.sync.aligned.m8n8.x4.shared.b16 {%0,%1,%2,%3}, [%4];"
                 : "=r"(r0), "=r"(r1), "=r"(r2), "=r"(r3) : "r"(addr));
}

__device__ __forceinline__ uint32_t smem_u32(const void* p) {
    uint32_t a;
    asm("{ .reg .u64 t; cvta.to.shared.u64 t, %1; cvt.u32.u64 %0, t; }" : "=r"(a) : "l"(p));
    return a;
}

// ---------------------------------------------------------------------------
// Stage 0: Wh[n][k] = fp16(W_cls[k][n])
// ---------------------------------------------------------------------------
__global__ __launch_bounds__(256)
void transpose_w(const float* __restrict__ W, __half* __restrict__ Wh) {
    __shared__ float t[32][33];
    int n0 = blockIdx.x * 32, k0 = blockIdx.y * 32;
    int tx = threadIdx.x, ty = threadIdx.y;   // (32, 8)
#pragma unroll
    for (int i = 0; i < 32; i += 8)
        t[ty + i][tx] = W[(size_t)(k0 + ty + i) * V_ + n0 + tx];
    __syncthreads();
#pragma unroll
    for (int i = 0; i < 32; i += 8)
        Wh[(size_t)(n0 + ty + i) * DJ + k0 + tx] = __float2half_rn(t[tx][ty + i]);
}

// ---------------------------------------------------------------------------
// Stage 1: small fp32 GEMM with bias, C[M,256] = A[M,K] @ W[K,256] + bias
// ---------------------------------------------------------------------------
__global__ __launch_bounds__(256)
void gemm_bias_f32(const float* __restrict__ A, const float* __restrict__ W,
                   const float* __restrict__ bias, float* __restrict__ C,
                   int M, int K) {
    const int N = DJ;
    __shared__ float As[16][68];
    __shared__ float Ws[16][68];

    int m0 = blockIdx.x * 64, n0 = blockIdx.y * 64;
    int tid = threadIdx.x;
    int ty = tid >> 4, tx = tid & 15;

    float acc[4][4];
#pragma unroll
    for (int i = 0; i < 4; i++)
#pragma unroll
        for (int j = 0; j < 4; j++) acc[i][j] = 0.f;

    for (int k0 = 0; k0 < K; k0 += 16) {
        {
            int row = tid >> 2, kc = (tid & 3) << 2;
            float4 v = make_float4(0.f, 0.f, 0.f, 0.f);
            int m = m0 + row;
            if (m < M) v = *(const float4*)(A + (size_t)m * K + k0 + kc);
            As[kc + 0][row] = v.x;
            As[kc + 1][row] = v.y;
            As[kc + 2][row] = v.z;
            As[kc + 3][row] = v.w;
        }
        {
            int kr = tid >> 4, nc = (tid & 15) << 2;
            float4 w = *(const float4*)(W + (size_t)(k0 + kr) * N + n0 + nc);
            *(float4*)&Ws[kr][nc] = w;
        }
        __syncthreads();
#pragma unroll
        for (int kk = 0; kk < 16; kk++) {
            float a[4], b[4];
#pragma unroll
            for (int i = 0; i < 4; i++) a[i] = As[kk][ty * 4 + i];
#pragma unroll
            for (int j = 0; j < 4; j++) b[j] = Ws[kk][tx * 4 + j];
#pragma unroll
            for (int i = 0; i < 4; i++)
#pragma unroll
                for (int j = 0; j < 4; j++) acc[i][j] = fmaf(a[i], b[j], acc[i][j]);
        }
        __syncthreads();
    }
#pragma unroll
    for (int i = 0; i < 4; i++) {
        int m = m0 + ty * 4 + i;
        if (m >= M) continue;
#pragma unroll
        for (int j = 0; j < 4; j++) {
            int n = n0 + tx * 4 + j;
            C[(size_t)m * N + n] = acc[i][j] + bias[n];
        }
    }
}

// ---------------------------------------------------------------------------
// Stage 2: Zh = fp16(tanh_hw(XT[bt,:] + YP[b*U+u,:]))
// ---------------------------------------------------------------------------
__global__ __launch_bounds__(256)
void z_tanh_kernel(const float* __restrict__ XT, const float* __restrict__ YP,
                   __half* __restrict__ Z) {
    int i = blockIdx.x * blockDim.x + threadIdx.x;      // 4-element group
    const int total4 = M_TOTAL * (DJ / 4);
    if (i >= total4) return;
    int m = i >> 6;
    int q = i & 63;
    int bt = m / U_;
    int u = m - bt * U_;
    int b = bt / T_;

    float4 xv = *(const float4*)(XT + (size_t)bt * DJ + q * 4);
    float4 yv = *(const float4*)(YP + (size_t)(b * U_ + u) * DJ + q * 4);
    __half2 h0 = __floats2half2_rn(fast_tanh(xv.x + yv.x), fast_tanh(xv.y + yv.y));
    __half2 h1 = __floats2half2_rn(fast_tanh(xv.z + yv.z), fast_tanh(xv.w + yv.w));
    __half2* dst = (__half2*)(Z + (size_t)m * DJ + q * 4);
    dst[0] = h0;
    dst[1] = h1;
}

// ---------------------------------------------------------------------------
// Stage 3: out = Zh @ Wh^T + b_cls via mma.sync.m16n8k16.f16 (fp32 accum).
// CTA 128M x 128N, 128 threads, 4 warps of 64x64 (2M x 2N).
// Tiles: 128 rows x 128B (64 halves = BK), chunk XOR swizzle
// (chunk ^= row&7) -> ldmatrix loads AND cp.async stores conflict-free.
// K=256 -> 4 chunks, 3-stage cp.async, 1 sync/chunk, 2 CTAs/SM.
// ---------------------------------------------------------------------------
#define BM 128
#define BN 128
#define BKH 64                                        // halves per chunk
#define ROWB 128                                      // bytes per tile row
#define A_STAGE_BYTES (BM * ROWB)                     // 16384
#define B_STAGE_BYTES (BN * ROWB)                     // 16384
#define STAGE_BYTES (A_STAGE_BYTES + B_STAGE_BYTES)   // 32768
#define NSTAGES 3
#define JSMEM (NSTAGES * STAGE_BYTES)                 // 98304
#define NCHUNKS (DJ / BKH)                            // 4

__global__ __launch_bounds__(128, 2)
void joint_gemm_f16(const __half* __restrict__ Z, const __half* __restrict__ Wh,
                    const float* __restrict__ bias, float* __restrict__ out) {
    extern __shared__ char sm[];
    const uint32_t smbase = smem_u32(sm);

    const int K = DJ;     // 256
    const int N = V_;     // 1024

    const int n0 = blockIdx.x * BN;
    const int m0 = blockIdx.y * BM;
    const int tid = threadIdx.x;
    const int lane = tid & 31, w = tid >> 5;
    const int warpM = w & 1, warpN = w >> 1;      // 2 x 2
    const int wm0 = warpM * 64, wn0 = warpN * 64;
    const int gid = lane >> 2, tig = lane & 3;

    // ldmatrix lane mapping: matrix j = lane>>3; row-low = (j&1)*8 + l8;
    // chunk low bit = j>>1; swizzle XOR value = l8 (rows are 8-aligned).
    const int l8 = lane & 7, j = lane >> 3;
    const uint32_t rowlow = (uint32_t)(((j & 1) << 3) + l8);
    const uint32_t cbit = (uint32_t)(j >> 1);
    const uint32_t xorv = (uint32_t)l8;
    const uint32_t aRow = ((uint32_t)wm0 + rowlow) * ROWB;                    // + fm*16*ROWB
    const uint32_t bRow = (uint32_t)A_STAGE_BYTES + ((uint32_t)wn0 + rowlow) * ROWB;  // + p*16*ROWB

    // cp.async: threads 0-7 = one row's 8 chunks (conflict-free 128B wavefronts,
    // coalesced 128B global segments). Warp covers 4 rows; 8 passes of 16 rows.
    const int lrow = tid >> 3;     // 0..15
    const int lchunk = tid & 7;    // 16B chunk within row

#define LOAD_TILE(c, s) do { \
    uint32_t _sb = smbase + (uint32_t)(s) * STAGE_BYTES; \
    _Pragma("unroll") \
    for (int p = 0; p < 8; p++) { \
        int _r = lrow + p * 16; \
        uint32_t _d = _sb + (uint32_t)_r * ROWB + \
                      ((uint32_t)(lchunk ^ (_r & 7)) << 4); \
        const __half* _a = Z + (size_t)(m0 + _r) * K + (c) * BKH + lchunk * 8; \
        const __half* _b = Wh + (size_t)(n0 + _r) * K + (c) * BKH + lchunk * 8; \
        asm volatile("cp.async.cg.shared.global [%0], [%1], 16;" \
                     :: "r"(_d), "l"(_a)); \
        asm volatile("cp.async.cg.shared.global [%0], [%1], 16;" \
                     :: "r"(_d + (uint32_t)A_STAGE_BYTES), "l"(_b)); \
    } \
    asm volatile("cp.async.commit_group;" ::: "memory"); \
} while (0)

    float acc[4][8][4];
#pragma unroll
    for (int fm = 0; fm < 4; fm++)
#pragma unroll
        for (int fn = 0; fn < 8; fn++)
#pragma unroll
            for (int r = 0; r < 4; r++) acc[fm][fn][r] = 0.f;

    LOAD_TILE(0, 0);
    LOAD_TILE(1, 1);

#pragma unroll 1
    for (int c = 0; c < NCHUNKS; c++) {
        if (c < NCHUNKS - 1) asm volatile("cp.async.wait_group 1;" ::: "memory");
        else                 asm volatile("cp.async.wait_group 0;" ::: "memory");
        __syncthreads();
        if (c + 2 < NCHUNKS) LOAD_TILE(c + 2, (c + 2) % NSTAGES);

        const uint32_t stg = smbase + (uint32_t)(c % NSTAGES) * STAGE_BYTES;
        const uint32_t aB = stg + aRow;
        const uint32_t bB = stg + bRow;
#pragma unroll
        for (int ks = 0; ks < 4; ks++) {              // 4 x k16 per chunk
            const uint32_t c0 = (uint32_t)(ks << 1);  // chunk index of k-low half
            const uint32_t ch = ((c0 + cbit) ^ xorv) << 4;
            uint32_t a[4][4], b[8][2];
#pragma unroll
            for (int fm = 0; fm < 4; fm++)
                ldsm_x4(a[fm][0], a[fm][1], a[fm][2], a[fm][3],
                        aB + (uint32_t)fm * (16 * ROWB) + ch);
#pragma unroll
            for (int p = 0; p < 4; p++) {
                uint32_t r0, r1, r2, r3;
                ldsm_x4(r0, r1, r2, r3, bB + (uint32_t)p * (16 * ROWB) + ch);
                b[2 * p][0] = r0;      // n-tile 2p,   k0-7
                b[2 * p + 1][0] = r1;  // n-tile 2p+1, k0-7
                b[2 * p][1] = r2;      // n-tile 2p,   k8-15
                b[2 * p + 1][1] = r3;  // n-tile 2p+1, k8-15
            }
#pragma unroll
            for (int fm = 0; fm < 4; fm++)
#pragma unroll
                for (int fn = 0; fn < 8; fn++) mma_f16(acc[fm][fn], a[fm], b[fn]);
        }
    }
#undef LOAD_TILE

    // epilogue: bias + store
#pragma unroll
    for (int fm = 0; fm < 4; fm++) {
        int r0 = m0 + wm0 + fm * 16 + gid;
#pragma unroll
        for (int fn = 0; fn < 8; fn++) {
            int cidx = n0 + wn0 + fn * 8 + 2 * tig;
            float bv0 = __ldg(bias + cidx);
            float bv1 = __ldg(bias + cidx + 1);
            float2 v0 = make_float2(acc[fm][fn][0] + bv0, acc[fm][fn][1] + bv1);
            float2 v1 = make_float2(acc[fm][fn][2] + bv0, acc[fm][fn][3] + bv1);
            *(float2*)(out + (size_t)r0 * N + cidx) = v0;
            *(float2*)(out + (size_t)(r0 + 8) * N + cidx) = v1;
        }
    }
}

// ---------------------------------------------------------------------------
extern "C" void kernel_launch(void* const* d_in, const int* in_sizes, int n_in,
                              void* d_out, int out_size) {
    const float* x     = (const float*)d_in[0];
    const float* y     = (const float*)d_in[1];
    const float* W_tr  = (const float*)d_in[2];
    const float* b_tr  = (const float*)d_in[3];
    const float* W_pr  = (const float*)d_in[4];
    const float* b_pr  = (const float*)d_in[5];
    const float* W_cls = (const float*)d_in[6];
    const float* b_cls = (const float*)d_in[7];
    float* out = (float*)d_out;

    void *pXT, *pYP, *pZh, *pWh;
    cudaGetSymbolAddress(&pXT, g_XT);
    cudaGetSymbolAddress(&pYP, g_YP);
    cudaGetSymbolAddress(&pZh, g_Zh);
    cudaGetSymbolAddress(&pWh, g_Wh);

    // Wh = fp16(W_cls^T)
    {
        dim3 grid(V_ / 32, DJ / 32);
        transpose_w<<<grid, dim3(32, 8)>>>(W_cls, (__half*)pWh);
    }
    // XT = x @ W_tr + b_tr
    {
        dim3 grid((B_ * T_ + 63) / 64, DJ / 64);
        gemm_bias_f32<<<grid, 256>>>(x, W_tr, b_tr, (float*)pXT, B_ * T_, DTR);
    }
    // YP = y @ W_pr + b_pr
    {
        dim3 grid((B_ * U_ + 63) / 64, DJ / 64);
        gemm_bias_f32<<<grid, 256>>>(y, W_pr, b_pr, (float*)pYP, B_ * U_, DPR);
    }
    // Zh = fp16(tanh(XT + YP))
    {
        int total4 = M_TOTAL * (DJ / 4);
        z_tanh_kernel<<<(total4 + 255) / 256, 256>>>((const float*)pXT,
                                                     (const float*)pYP, (__half*)pZh);
    }
    // out = Zh @ Wh^T + b_cls
    {
        cudaFuncSetAttribute(joint_gemm_f16, cudaFuncAttributeMaxDynamicSharedMemorySize,
                             JSMEM);
        dim3 grid(V_ / BN, M_TOTAL / BM);   // (8, 1250), N fastest for Z reuse
        joint_gemm_f16<<<grid, 128, JSMEM>>>((const __half*)pZh, (const __half*)pWh,
                                             b_cls, out);
    }
}

// round 8
// speedup vs baseline: 2.2547x; 1.0102x over previous
#include <cuda_runtime.h>
#include <cuda_fp16.h>
#include <cstdint>

// ---------------------------------------------------------------------------
// RNN-T joint network (sm_103 legacy tensor path, fp16 mma):
//   XT = x@W_tr + b_tr            [1600, 256]  fp32
//   YP = y@W_pr + b_pr            [400, 256]   fp32
//   Zh = fp16(tanh(XT[bt] + YP[b,u]))  [160000, 256]
//   out= Zh @ Wh + b_cls          [160000, 1024]  mma.sync m16n8k16 f16,f32acc
// Joint GEMM: PERSISTENT CTAs (296 = 2/SM), B tile resident in SMEM (loaded
// once), A streamed via continuous 3-stage cp.async ring across tile bounds.
// ---------------------------------------------------------------------------

#define B_  4
#define T_  400
#define U_  100
#define DTR 768
#define DPR 640
#define DJ  256
#define V_  1024
#define M_TOTAL (B_ * T_ * U_)   // 160000

__device__ float  g_XT[(size_t)B_ * T_ * DJ];
__device__ float  g_YP[(size_t)B_ * U_ * DJ];
__device__ __half g_Zh[(size_t)M_TOTAL * DJ];   // 82 MB
__device__ __half g_Wh[(size_t)V_ * DJ];        // fp16(W_cls^T), n-major [V][DJ]

__device__ __forceinline__ float fast_tanh(float x) {
    float r;
    asm("tanh.approx.f32 %0, %1;" : "=f"(r) : "f"(x));
    return r;
}

__device__ __forceinline__ void mma_f16(float* c, const uint32_t* a, const uint32_t* b) {
    asm volatile(
        "mma.sync.aligned.m16n8k16.row.col.f32.f16.f16.f32 "
        "{%0,%1,%2,%3}, {%4,%5,%6,%7}, {%8,%9}, {%0,%1,%2,%3};\n"
        : "+f"(c[0]), "+f"(c[1]), "+f"(c[2]), "+f"(c[3])
        : "r"(a[0]), "r"(a[1]), "r"(a[2]), "r"(a[3]), "r"(b[0]), "r"(b[1]));
}

__device__ __forceinline__ void ldsm_x4(uint32_t& r0, uint32_t& r1, uint32_t& r2,
                                        uint32_t& r3, uint32_t addr) {
    asm volatile("ldmatrix.sync.aligned.m8n8.x4.shared.b16 {%0,%1,%2,%3}, [%4];"
                 : "=r"(r0), "=r"(r1), "=r"(r2), "=r"(r3) : "r"(addr));
}

__device__ __forceinline__ uint32_t smem_u32(const void* p) {
    uint32_t a;
    asm("{ .reg .u64 t; cvta.to.shared.u64 t, %1; cvt.u32.u64 %0, t; }" : "=r"(a) : "l"(p));
    return a;
}

// ---------------------------------------------------------------------------
// Stage 0: Wh[n][k] = fp16(W_cls[k][n])
// ---------------------------------------------------------------------------
__global__ __launch_bounds__(256)
void transpose_w(const float* __restrict__ W, __half* __restrict__ Wh) {
    __shared__ float t[32][33];
    int n0 = blockIdx.x * 32, k0 = blockIdx.y * 32;
    int tx = threadIdx.x, ty = threadIdx.y;   // (32, 8)
#pragma unroll
    for (int i = 0; i < 32; i += 8)
        t[ty + i][tx] = W[(size_t)(k0 + ty + i) * V_ + n0 + tx];
    __syncthreads();
#pragma unroll
    for (int i = 0; i < 32; i += 8)
        Wh[(size_t)(n0 + ty + i) * DJ + k0 + tx] = __float2half_rn(t[tx][ty + i]);
}

// ---------------------------------------------------------------------------
// Stage 1: small fp32 GEMM with bias, C[M,256] = A[M,K] @ W[K,256] + bias
// ---------------------------------------------------------------------------
__global__ __launch_bounds__(256)
void gemm_bias_f32(const float* __restrict__ A, const float* __restrict__ W,
                   const float* __restrict__ bias, float* __restrict__ C,
                   int M, int K) {
    const int N = DJ;
    __shared__ float As[16][68];
    __shared__ float Ws[16][68];

    int m0 = blockIdx.x * 64, n0 = blockIdx.y * 64;
    int tid = threadIdx.x;
    int ty = tid >> 4, tx = tid & 15;

    float acc[4][4];
#pragma unroll
    for (int i = 0; i < 4; i++)
#pragma unroll
        for (int j = 0; j < 4; j++) acc[i][j] = 0.f;

    for (int k0 = 0; k0 < K; k0 += 16) {
        {
            int row = tid >> 2, kc = (tid & 3) << 2;
            float4 v = make_float4(0.f, 0.f, 0.f, 0.f);
            int m = m0 + row;
            if (m < M) v = *(const float4*)(A + (size_t)m * K + k0 + kc);
            As[kc + 0][row] = v.x;
            As[kc + 1][row] = v.y;
            As[kc + 2][row] = v.z;
            As[kc + 3][row] = v.w;
        }
        {
            int kr = tid >> 4, nc = (tid & 15) << 2;
            float4 w = *(const float4*)(W + (size_t)(k0 + kr) * N + n0 + nc);
            *(float4*)&Ws[kr][nc] = w;
        }
        __syncthreads();
#pragma unroll
        for (int kk = 0; kk < 16; kk++) {
            float a[4], b[4];
#pragma unroll
            for (int i = 0; i < 4; i++) a[i] = As[kk][ty * 4 + i];
#pragma unroll
            for (int j = 0; j < 4; j++) b[j] = Ws[kk][tx * 4 + j];
#pragma unroll
            for (int i = 0; i < 4; i++)
#pragma unroll
                for (int j = 0; j < 4; j++) acc[i][j] = fmaf(a[i], b[j], acc[i][j]);
        }
        __syncthreads();
    }
#pragma unroll
    for (int i = 0; i < 4; i++) {
        int m = m0 + ty * 4 + i;
        if (m >= M) continue;
#pragma unroll
        for (int j = 0; j < 4; j++) {
            int n = n0 + tx * 4 + j;
            C[(size_t)m * N + n] = acc[i][j] + bias[n];
        }
    }
}

// ---------------------------------------------------------------------------
// Stage 2: Zh = fp16(tanh_hw(XT[bt,:] + YP[b*U+u,:]))
// ---------------------------------------------------------------------------
__global__ __launch_bounds__(256)
void z_tanh_kernel(const float* __restrict__ XT, const float* __restrict__ YP,
                   __half* __restrict__ Z) {
    int i = blockIdx.x * blockDim.x + threadIdx.x;      // 4-element group
    const int total4 = M_TOTAL * (DJ / 4);
    if (i >= total4) return;
    int m = i >> 6;
    int q = i & 63;
    int bt = m / U_;
    int u = m - bt * U_;
    int b = bt / T_;

    float4 xv = *(const float4*)(XT + (size_t)bt * DJ + q * 4);
    float4 yv = *(const float4*)(YP + (size_t)(b * U_ + u) * DJ + q * 4);
    __half2 h0 = __floats2half2_rn(fast_tanh(xv.x + yv.x), fast_tanh(xv.y + yv.y));
    __half2 h1 = __floats2half2_rn(fast_tanh(xv.z + yv.z), fast_tanh(xv.w + yv.w));
    __half2* dst = (__half2*)(Z + (size_t)m * DJ + q * 4);
    dst[0] = h0;
    dst[1] = h1;
}

// ---------------------------------------------------------------------------
// Stage 3: out = Zh @ Wh^T + b_cls, persistent CTAs.
// 296 CTAs (2/SM): CTA c -> n-tile (c&7), m-group (c>>3); loops m-tiles
// t = mgroup, mgroup+37, ...  (8 CTAs of a group stay wave-aligned -> A L2 hot)
// B: [128 n][256 k] fp16 = 64KB resident in smem (512B rows, chunk^=(row&7)).
// A: 3-stage ring of 16KB k-chunks (128B rows, chunk^=(row&7)), cp.async
// streamed continuously across tile boundaries (1 commit/iteration).
// ---------------------------------------------------------------------------
#define BM 128
#define BN 128
#define BKH 64                                  // halves per A chunk
#define ROWB 128                                // A tile row bytes
#define A_STAGE_BYTES (BM * ROWB)               // 16384
#define NSTAGES 3
#define B_BYTES (BN * DJ * 2)                   // 65536
#define B_OFF (NSTAGES * A_STAGE_BYTES)         // 49152
#define JSMEM (B_OFF + B_BYTES)                 // 114688
#define NCHUNKS (DJ / BKH)                      // 4
#define MGROUPS 37
#define MTILES (M_TOTAL / BM)                   // 1250
#define NJCTAS (8 * MGROUPS)                    // 296

__global__ __launch_bounds__(128, 2)
void joint_gemm_f16(const __half* __restrict__ Z, const __half* __restrict__ Wh,
                    const float* __restrict__ bias, float* __restrict__ out) {
    extern __shared__ char sm[];
    const uint32_t smbase = smem_u32(sm);
    const uint32_t bbase = smbase + B_OFF;

    const int K = DJ;     // 256
    const int N = V_;     // 1024

    const int n0 = (blockIdx.x & 7) * BN;
    const int mgroup = blockIdx.x >> 3;         // 0..36
    const int tid = threadIdx.x;
    const int lane = tid & 31, w = tid >> 5;
    const int warpM = w & 1, warpN = w >> 1;    // 2 x 2
    const int wm0 = warpM * 64, wn0 = warpN * 64;
    const int gid = lane >> 2, tig = lane & 3;

    // ldmatrix lane mapping (as R7): matrix j = lane>>3; row-low = (j&1)*8+l8;
    // chunk low bit = j>>1; swizzle XOR value = l8.
    const int l8 = lane & 7, j = lane >> 3;
    const uint32_t rowlow = (uint32_t)(((j & 1) << 3) + l8);
    const uint32_t cbit = (uint32_t)(j >> 1);
    const uint32_t xorv = (uint32_t)l8;
    const uint32_t aRow = ((uint32_t)wm0 + rowlow) * ROWB;          // + fm*16*ROWB
    const uint32_t bRow = bbase + ((uint32_t)wn0 + rowlow) * 512;   // + p*16*512

    // ------- one-time B load: rows = n, 512B each, swizzled 16B chunks -------
    {
        int r = tid;                    // 0..127 (n-row)
        const __half* src = Wh + (size_t)(n0 + r) * K;
        uint32_t dbase = bbase + (uint32_t)r * 512;
        uint32_t rx = (uint32_t)(r & 7);
#pragma unroll
        for (int ch = 0; ch < 32; ch++) {
            uint32_t d = dbase + (((uint32_t)ch ^ rx) << 4);
            asm volatile("cp.async.cg.shared.global [%0], [%1], 16;"
                         :: "r"(d), "l"(src + ch * 8));
        }
        asm volatile("cp.async.commit_group;" ::: "memory");
    }

    // ------- A streaming: 128 rows x 128B per chunk -------
    const int lrow = tid >> 3;     // 0..15
    const int lchunk = tid & 7;    // 16B chunk within 128B row

#define LOAD_A(mt, c, s) do { \
    uint32_t _sb = smbase + (uint32_t)(s) * A_STAGE_BYTES; \
    _Pragma("unroll") \
    for (int p = 0; p < 8; p++) { \
        int _r = lrow + p * 16; \
        uint32_t _d = _sb + (uint32_t)_r * ROWB + \
                      ((uint32_t)(lchunk ^ (_r & 7)) << 4); \
        const __half* _a = Z + (size_t)((mt) * BM + _r) * K + (c) * BKH + lchunk * 8; \
        asm volatile("cp.async.cg.shared.global [%0], [%1], 16;" \
                     :: "r"(_d), "l"(_a)); \
    } \
    asm volatile("cp.async.commit_group;" ::: "memory"); \
} while (0)

    // load cursor
    int lt = mgroup;     // m-tile being loaded (-1 = exhausted)
    int lc = 0;          // chunk within tile
    int ls = 0;          // stage ring
#define ADV_LOAD() do { \
    if (++lc == NCHUNKS) { lc = 0; lt += MGROUPS; if (lt >= MTILES) lt = -1; } \
    ls = (ls + 1 == NSTAGES) ? 0 : ls + 1; \
} while (0)

    LOAD_A(lt, lc, ls); ADV_LOAD();
    LOAD_A(lt, lc, ls); ADV_LOAD();

    int cs = 0;          // consume stage ring

#pragma unroll 1
    for (int t = mgroup; t < MTILES; t += MGROUPS) {
        const int m0 = t * BM;
        const bool lastTile = (t + MGROUPS >= MTILES);

        float acc[4][8][4];
#pragma unroll
        for (int fm = 0; fm < 4; fm++)
#pragma unroll
            for (int fn = 0; fn < 8; fn++)
#pragma unroll
                for (int r = 0; r < 4; r++) acc[fm][fn][r] = 0.f;

#pragma unroll
        for (int c = 0; c < NCHUNKS; c++) {
            if (lastTile && c == NCHUNKS - 1)
                asm volatile("cp.async.wait_group 0;" ::: "memory");
            else
                asm volatile("cp.async.wait_group 1;" ::: "memory");
            __syncthreads();
            if (lt >= 0) { LOAD_A(lt, lc, ls); ADV_LOAD(); }

            const uint32_t aB = smbase + (uint32_t)cs * A_STAGE_BYTES + aRow;
            cs = (cs + 1 == NSTAGES) ? 0 : cs + 1;
#pragma unroll
            for (int ks = 0; ks < 4; ks++) {              // 4 x k16 per chunk
                // A: chunk within stage (8 x 16B), swizzled
                const uint32_t aCh = (((uint32_t)(ks << 1) + cbit) ^ xorv) << 4;
                // B: global 16B chunk within 512B row, swizzled (xor hits low 3 bits)
                const uint32_t bCh = (((uint32_t)(c * 8 + (ks << 1)) + cbit) ^ xorv) << 4;
                uint32_t a[4][4], b[8][2];
#pragma unroll
                for (int fm = 0; fm < 4; fm++)
                    ldsm_x4(a[fm][0], a[fm][1], a[fm][2], a[fm][3],
                            aB + (uint32_t)fm * (16 * ROWB) + aCh);
#pragma unroll
                for (int p = 0; p < 4; p++) {
                    uint32_t r0, r1, r2, r3;
                    ldsm_x4(r0, r1, r2, r3, bRow + (uint32_t)p * (16 * 512) + bCh);
                    b[2 * p][0] = r0;
                    b[2 * p + 1][0] = r1;
                    b[2 * p][1] = r2;
                    b[2 * p + 1][1] = r3;
                }
#pragma unroll
                for (int fm = 0; fm < 4; fm++)
#pragma unroll
                    for (int fn = 0; fn < 8; fn++) mma_f16(acc[fm][fn], a[fm], b[fn]);
            }
        }

        // epilogue: bias + store
#pragma unroll
        for (int fm = 0; fm < 4; fm++) {
            int r0 = m0 + wm0 + fm * 16 + gid;
#pragma unroll
            for (int fn = 0; fn < 8; fn++) {
                int cidx = n0 + wn0 + fn * 8 + 2 * tig;
                float bv0 = __ldg(bias + cidx);
                float bv1 = __ldg(bias + cidx + 1);
                float2 v0 = make_float2(acc[fm][fn][0] + bv0, acc[fm][fn][1] + bv1);
                float2 v1 = make_float2(acc[fm][fn][2] + bv0, acc[fm][fn][3] + bv1);
                *(float2*)(out + (size_t)r0 * N + cidx) = v0;
                *(float2*)(out + (size_t)(r0 + 8) * N + cidx) = v1;
            }
        }
    }
#undef LOAD_A
#undef ADV_LOAD
}

// ---------------------------------------------------------------------------
extern "C" void kernel_launch(void* const* d_in, const int* in_sizes, int n_in,
                              void* d_out, int out_size) {
    const float* x     = (const float*)d_in[0];
    const float* y     = (const float*)d_in[1];
    const float* W_tr  = (const float*)d_in[2];
    const float* b_tr  = (const float*)d_in[3];
    const float* W_pr  = (const float*)d_in[4];
    const float* b_pr  = (const float*)d_in[5];
    const float* W_cls = (const float*)d_in[6];
    const float* b_cls = (const float*)d_in[7];
    float* out = (float*)d_out;

    void *pXT, *pYP, *pZh, *pWh;
    cudaGetSymbolAddress(&pXT, g_XT);
    cudaGetSymbolAddress(&pYP, g_YP);
    cudaGetSymbolAddress(&pZh, g_Zh);
    cudaGetSymbolAddress(&pWh, g_Wh);

    // Wh = fp16(W_cls^T)
    {
        dim3 grid(V_ / 32, DJ / 32);
        transpose_w<<<grid, dim3(32, 8)>>>(W_cls, (__half*)pWh);
    }
    // XT = x @ W_tr + b_tr
    {
        dim3 grid((B_ * T_ + 63) / 64, DJ / 64);
        gemm_bias_f32<<<grid, 256>>>(x, W_tr, b_tr, (float*)pXT, B_ * T_, DTR);
    }
    // YP = y @ W_pr + b_pr
    {
        dim3 grid((B_ * U_ + 63) / 64, DJ / 64);
        gemm_bias_f32<<<grid, 256>>>(y, W_pr, b_pr, (float*)pYP, B_ * U_, DPR);
    }
    // Zh = fp16(tanh(XT + YP))
    {
        int total4 = M_TOTAL * (DJ / 4);
        z_tanh_kernel<<<(total4 + 255) / 256, 256>>>((const float*)pXT,
                                                     (const float*)pYP, (__half*)pZh);
    }
    // out = Zh @ Wh^T + b_cls  (persistent)
    {
        cudaFuncSetAttribute(joint_gemm_f16, cudaFuncAttributeMaxDynamicSharedMemorySize,
                             JSMEM);
        joint_gemm_f16<<<NJCTAS, 128, JSMEM>>>((const __half*)pZh, (const __half*)pWh,
                                               b_cls, out);
    }
}

// round 9
// speedup vs baseline: 2.2900x; 1.0156x over previous
#include <cuda_runtime.h>
#include <cuda_fp16.h>
#include <cstdint>

// ---------------------------------------------------------------------------
// RNN-T joint network (sm_103 legacy tensor path, fp16 mma):
//   XT = x@W_tr + b_tr            [1600, 256]  fp32
//   YP = y@W_pr + b_pr            [400, 256]   fp32
//   Zh = fp16(tanh(XT[bt] + YP[b,u]))  [160000, 256]
//   out= Zh @ Wh + b_cls          [160000, 1024]  mma.sync m16n8k16 f16,f32acc
// Joint GEMM: persistent CTAs (296 = 2/SM), B resident in smem, A streamed
// via continuous 3-stage cp.async ring, bias hoisted to registers.
// z_tanh: block-per-bt, XT row in registers, streaming half2 stores.
// ---------------------------------------------------------------------------

#define B_  4
#define T_  400
#define U_  100
#define DTR 768
#define DPR 640
#define DJ  256
#define V_  1024
#define M_TOTAL (B_ * T_ * U_)   // 160000

__device__ float  g_XT[(size_t)B_ * T_ * DJ];
__device__ float  g_YP[(size_t)B_ * U_ * DJ];
__device__ __half g_Zh[(size_t)M_TOTAL * DJ];   // 82 MB
__device__ __half g_Wh[(size_t)V_ * DJ];        // fp16(W_cls^T), n-major [V][DJ]

__device__ __forceinline__ float fast_tanh(float x) {
    float r;
    asm("tanh.approx.f32 %0, %1;" : "=f"(r) : "f"(x));
    return r;
}

__device__ __forceinline__ void mma_f16(float* c, const uint32_t* a, const uint32_t* b) {
    asm volatile(
        "mma.sync.aligned.m16n8k16.row.col.f32.f16.f16.f32 "
        "{%0,%1,%2,%3}, {%4,%5,%6,%7}, {%8,%9}, {%0,%1,%2,%3};\n"
        : "+f"(c[0]), "+f"(c[1]), "+f"(c[2]), "+f"(c[3])
        : "r"(a[0]), "r"(a[1]), "r"(a[2]), "r"(a[3]), "r"(b[0]), "r"(b[1]));
}

__device__ __forceinline__ void ldsm_x4(uint32_t& r0, uint32_t& r1, uint32_t& r2,
                                        uint32_t& r3, uint32_t addr) {
    asm volatile("ldmatrix.sync.aligned.m8n8.x4.shared.b16 {%0,%1,%2,%3}, [%4];"
                 : "=r"(r0), "=r"(r1), "=r"(r2), "=r"(r3) : "r"(addr));
}

__device__ __forceinline__ uint32_t smem_u32(const void* p) {
    uint32_t a;
    asm("{ .reg .u64 t; cvta.to.shared.u64 t, %1; cvt.u32.u64 %0, t; }" : "=r"(a) : "l"(p));
    return a;
}

// ---------------------------------------------------------------------------
// Stage 0: Wh[n][k] = fp16(W_cls[k][n])
// ---------------------------------------------------------------------------
__global__ __launch_bounds__(256)
void transpose_w(const float* __restrict__ W, __half* __restrict__ Wh) {
    __shared__ float t[32][33];
    int n0 = blockIdx.x * 32, k0 = blockIdx.y * 32;
    int tx = threadIdx.x, ty = threadIdx.y;   // (32, 8)
#pragma unroll
    for (int i = 0; i < 32; i += 8)
        t[ty + i][tx] = W[(size_t)(k0 + ty + i) * V_ + n0 + tx];
    __syncthreads();
#pragma unroll
    for (int i = 0; i < 32; i += 8)
        Wh[(size_t)(n0 + ty + i) * DJ + k0 + tx] = __float2half_rn(t[tx][ty + i]);
}

// ---------------------------------------------------------------------------
// Stage 1: small fp32 GEMM with bias, C[M,256] = A[M,K] @ W[K,256] + bias
// ---------------------------------------------------------------------------
__global__ __launch_bounds__(256)
void gemm_bias_f32(const float* __restrict__ A, const float* __restrict__ W,
                   const float* __restrict__ bias, float* __restrict__ C,
                   int M, int K) {
    const int N = DJ;
    __shared__ float As[16][68];
    __shared__ float Ws[16][68];

    int m0 = blockIdx.x * 64, n0 = blockIdx.y * 64;
    int tid = threadIdx.x;
    int ty = tid >> 4, tx = tid & 15;

    float acc[4][4];
#pragma unroll
    for (int i = 0; i < 4; i++)
#pragma unroll
        for (int j = 0; j < 4; j++) acc[i][j] = 0.f;

    for (int k0 = 0; k0 < K; k0 += 16) {
        {
            int row = tid >> 2, kc = (tid & 3) << 2;
            float4 v = make_float4(0.f, 0.f, 0.f, 0.f);
            int m = m0 + row;
            if (m < M) v = *(const float4*)(A + (size_t)m * K + k0 + kc);
            As[kc + 0][row] = v.x;
            As[kc + 1][row] = v.y;
            As[kc + 2][row] = v.z;
            As[kc + 3][row] = v.w;
        }
        {
            int kr = tid >> 4, nc = (tid & 15) << 2;
            float4 w = *(const float4*)(W + (size_t)(k0 + kr) * N + n0 + nc);
            *(float4*)&Ws[kr][nc] = w;
        }
        __syncthreads();
#pragma unroll
        for (int kk = 0; kk < 16; kk++) {
            float a[4], b[4];
#pragma unroll
            for (int i = 0; i < 4; i++) a[i] = As[kk][ty * 4 + i];
#pragma unroll
            for (int j = 0; j < 4; j++) b[j] = Ws[kk][tx * 4 + j];
#pragma unroll
            for (int i = 0; i < 4; i++)
#pragma unroll
                for (int j = 0; j < 4; j++) acc[i][j] = fmaf(a[i], b[j], acc[i][j]);
        }
        __syncthreads();
    }
#pragma unroll
    for (int i = 0; i < 4; i++) {
        int m = m0 + ty * 4 + i;
        if (m >= M) continue;
#pragma unroll
        for (int j = 0; j < 4; j++) {
            int n = n0 + tx * 4 + j;
            C[(size_t)m * N + n] = acc[i][j] + bias[n];
        }
    }
}

// ---------------------------------------------------------------------------
// Stage 2: Zh = fp16(tanh_hw(XT[bt,:] + YP[b*U+u,:]))
// Block per bt (grid 1600, block 256). XT row cached: one smem pass, then
// each thread keeps its 2 columns in registers across all u. Threads split
// into 2 half-blocks handling interleaved u values. No div/mod in the loop.
// ---------------------------------------------------------------------------
__global__ __launch_bounds__(256)
void z_tanh_kernel(const float* __restrict__ XT, const float* __restrict__ YP,
                   __half* __restrict__ Z) {
    __shared__ float xs[DJ];
    const int bt = blockIdx.x;          // 0..1599
    const int b = bt / T_;
    const int tid = threadIdx.x;

    xs[tid] = XT[(size_t)bt * DJ + tid];
    __syncthreads();

    const int half = tid >> 7;          // 0/1: u parity
    const int c2 = (tid & 127) * 2;     // column pair
    const float x0 = xs[c2];
    const float x1 = xs[c2 + 1];

    __half* zrow = Z + (size_t)bt * U_ * DJ + c2;
    const float* yb = YP + (size_t)b * U_ * DJ + c2;

#pragma unroll 2
    for (int u = half; u < U_; u += 2) {
        float2 yv = *(const float2*)(yb + (size_t)u * DJ);
        __half2 h = __floats2half2_rn(fast_tanh(x0 + yv.x), fast_tanh(x1 + yv.y));
        *(__half2*)(zrow + (size_t)u * DJ) = h;
    }
}

// ---------------------------------------------------------------------------
// Stage 3: out = Zh @ Wh^T + b_cls, persistent CTAs.
// 296 CTAs (2/SM): CTA c -> n-tile (c&7), m-group (c>>3); loops m-tiles
// t = mgroup, mgroup+37, ...  B resident in smem (512B rows, chunk^=(row&7)).
// A: 3-stage ring of 16KB k-chunks, cp.async streamed continuously.
// Bias hoisted into 16 registers before the loop.
// ---------------------------------------------------------------------------
#define BM 128
#define BN 128
#define BKH 64                                  // halves per A chunk
#define ROWB 128                                // A tile row bytes
#define A_STAGE_BYTES (BM * ROWB)               // 16384
#define NSTAGES 3
#define B_BYTES (BN * DJ * 2)                   // 65536
#define B_OFF (NSTAGES * A_STAGE_BYTES)         // 49152
#define JSMEM (B_OFF + B_BYTES)                 // 114688
#define NCHUNKS (DJ / BKH)                      // 4
#define MGROUPS 37
#define MTILES (M_TOTAL / BM)                   // 1250
#define NJCTAS (8 * MGROUPS)                    // 296

__global__ __launch_bounds__(128, 2)
void joint_gemm_f16(const __half* __restrict__ Z, const __half* __restrict__ Wh,
                    const float* __restrict__ bias, float* __restrict__ out) {
    extern __shared__ char sm[];
    const uint32_t smbase = smem_u32(sm);
    const uint32_t bbase = smbase + B_OFF;

    const int K = DJ;     // 256
    const int N = V_;     // 1024

    const int n0 = (blockIdx.x & 7) * BN;
    const int mgroup = blockIdx.x >> 3;         // 0..36
    const int tid = threadIdx.x;
    const int lane = tid & 31, w = tid >> 5;
    const int warpM = w & 1, warpN = w >> 1;    // 2 x 2
    const int wm0 = warpM * 64, wn0 = warpN * 64;
    const int gid = lane >> 2, tig = lane & 3;

    // ldmatrix lane mapping: matrix j = lane>>3; row-low = (j&1)*8+l8;
    // chunk low bit = j>>1; swizzle XOR value = l8.
    const int l8 = lane & 7, j = lane >> 3;
    const uint32_t rowlow = (uint32_t)(((j & 1) << 3) + l8);
    const uint32_t cbit = (uint32_t)(j >> 1);
    const uint32_t xorv = (uint32_t)l8;
    const uint32_t aRow = ((uint32_t)wm0 + rowlow) * ROWB;          // + fm*16*ROWB
    const uint32_t bRow = bbase + ((uint32_t)wn0 + rowlow) * 512;   // + p*16*512

    // bias hoist: the only 16 bias values this thread ever uses
    float bv[8][2];
#pragma unroll
    for (int fn = 0; fn < 8; fn++) {
        int cidx = n0 + wn0 + fn * 8 + 2 * tig;
        bv[fn][0] = bias[cidx];
        bv[fn][1] = bias[cidx + 1];
    }

    // ------- one-time B load: rows = n, 512B each, swizzled 16B chunks -------
    {
        int r = tid;                    // 0..127 (n-row)
        const __half* src = Wh + (size_t)(n0 + r) * K;
        uint32_t dbase = bbase + (uint32_t)r * 512;
        uint32_t rx = (uint32_t)(r & 7);
#pragma unroll
        for (int ch = 0; ch < 32; ch++) {
            uint32_t d = dbase + (((uint32_t)ch ^ rx) << 4);
            asm volatile("cp.async.cg.shared.global [%0], [%1], 16;"
                         :: "r"(d), "l"(src + ch * 8));
        }
        asm volatile("cp.async.commit_group;" ::: "memory");
    }

    // ------- A streaming: 128 rows x 128B per chunk -------
    const int lrow = tid >> 3;     // 0..15
    const int lchunk = tid & 7;    // 16B chunk within 128B row

#define LOAD_A(mt, c, s) do { \
    uint32_t _sb = smbase + (uint32_t)(s) * A_STAGE_BYTES; \
    _Pragma("unroll") \
    for (int p = 0; p < 8; p++) { \
        int _r = lrow + p * 16; \
        uint32_t _d = _sb + (uint32_t)_r * ROWB + \
                      ((uint32_t)(lchunk ^ (_r & 7)) << 4); \
        const __half* _a = Z + (size_t)((mt) * BM + _r) * K + (c) * BKH + lchunk * 8; \
        asm volatile("cp.async.cg.shared.global [%0], [%1], 16;" \
                     :: "r"(_d), "l"(_a)); \
    } \
    asm volatile("cp.async.commit_group;" ::: "memory"); \
} while (0)

    // load cursor
    int lt = mgroup;     // m-tile being loaded (-1 = exhausted)
    int lc = 0;          // chunk within tile
    int ls = 0;          // stage ring
#define ADV_LOAD() do { \
    if (++lc == NCHUNKS) { lc = 0; lt += MGROUPS; if (lt >= MTILES) lt = -1; } \
    ls = (ls + 1 == NSTAGES) ? 0 : ls + 1; \
} while (0)

    LOAD_A(lt, lc, ls); ADV_LOAD();
    LOAD_A(lt, lc, ls); ADV_LOAD();

    int cs = 0;          // consume stage ring

#pragma unroll 1
    for (int t = mgroup; t < MTILES; t += MGROUPS) {
        const int m0 = t * BM;
        const bool lastTile = (t + MGROUPS >= MTILES);

        float acc[4][8][4];
#pragma unroll
        for (int fm = 0; fm < 4; fm++)
#pragma unroll
            for (int fn = 0; fn < 8; fn++)
#pragma unroll
                for (int r = 0; r < 4; r++) acc[fm][fn][r] = 0.f;

#pragma unroll
        for (int c = 0; c < NCHUNKS; c++) {
            if (lastTile && c == NCHUNKS - 1)
                asm volatile("cp.async.wait_group 0;" ::: "memory");
            else
                asm volatile("cp.async.wait_group 1;" ::: "memory");
            __syncthreads();
            if (lt >= 0) { LOAD_A(lt, lc, ls); ADV_LOAD(); }

            const uint32_t aB = smbase + (uint32_t)cs * A_STAGE_BYTES + aRow;
            cs = (cs + 1 == NSTAGES) ? 0 : cs + 1;
#pragma unroll
            for (int ks = 0; ks < 4; ks++) {              // 4 x k16 per chunk
                const uint32_t aCh = (((uint32_t)(ks << 1) + cbit) ^ xorv) << 4;
                const uint32_t bCh = (((uint32_t)(c * 8 + (ks << 1)) + cbit) ^ xorv) << 4;
                uint32_t a[4][4], b[8][2];
#pragma unroll
                for (int fm = 0; fm < 4; fm++)
                    ldsm_x4(a[fm][0], a[fm][1], a[fm][2], a[fm][3],
                            aB + (uint32_t)fm * (16 * ROWB) + aCh);
#pragma unroll
                for (int p = 0; p < 4; p++) {
                    uint32_t r0, r1, r2, r3;
                    ldsm_x4(r0, r1, r2, r3, bRow + (uint32_t)p * (16 * 512) + bCh);
                    b[2 * p][0] = r0;
                    b[2 * p + 1][0] = r1;
                    b[2 * p][1] = r2;
                    b[2 * p + 1][1] = r3;
                }
#pragma unroll
                for (int fm = 0; fm < 4; fm++)
#pragma unroll
                    for (int fn = 0; fn < 8; fn++) mma_f16(acc[fm][fn], a[fm], b[fn]);
            }
        }

        // epilogue: bias (registers) + store
#pragma unroll
        for (int fm = 0; fm < 4; fm++) {
            int r0 = m0 + wm0 + fm * 16 + gid;
#pragma unroll
            for (int fn = 0; fn < 8; fn++) {
                int cidx = n0 + wn0 + fn * 8 + 2 * tig;
                float2 v0 = make_float2(acc[fm][fn][0] + bv[fn][0],
                                        acc[fm][fn][1] + bv[fn][1]);
                float2 v1 = make_float2(acc[fm][fn][2] + bv[fn][0],
                                        acc[fm][fn][3] + bv[fn][1]);
                *(float2*)(out + (size_t)r0 * N + cidx) = v0;
                *(float2*)(out + (size_t)(r0 + 8) * N + cidx) = v1;
            }
        }
    }
#undef LOAD_A
#undef ADV_LOAD
}

// ---------------------------------------------------------------------------
extern "C" void kernel_launch(void* const* d_in, const int* in_sizes, int n_in,
                              void* d_out, int out_size) {
    const float* x     = (const float*)d_in[0];
    const float* y     = (const float*)d_in[1];
    const float* W_tr  = (const float*)d_in[2];
    const float* b_tr  = (const float*)d_in[3];
    const float* W_pr  = (const float*)d_in[4];
    const float* b_pr  = (const float*)d_in[5];
    const float* W_cls = (const float*)d_in[6];
    const float* b_cls = (const float*)d_in[7];
    float* out = (float*)d_out;

    void *pXT, *pYP, *pZh, *pWh;
    cudaGetSymbolAddress(&pXT, g_XT);
    cudaGetSymbolAddress(&pYP, g_YP);
    cudaGetSymbolAddress(&pZh, g_Zh);
    cudaGetSymbolAddress(&pWh, g_Wh);

    // Wh = fp16(W_cls^T)
    {
        dim3 grid(V_ / 32, DJ / 32);
        transpose_w<<<grid, dim3(32, 8)>>>(W_cls, (__half*)pWh);
    }
    // XT = x @ W_tr + b_tr
    {
        dim3 grid((B_ * T_ + 63) / 64, DJ / 64);
        gemm_bias_f32<<<grid, 256>>>(x, W_tr, b_tr, (float*)pXT, B_ * T_, DTR);
    }
    // YP = y @ W_pr + b_pr
    {
        dim3 grid((B_ * U_ + 63) / 64, DJ / 64);
        gemm_bias_f32<<<grid, 256>>>(y, W_pr, b_pr, (float*)pYP, B_ * U_, DPR);
    }
    // Zh = fp16(tanh(XT + YP))
    z_tanh_kernel<<<B_ * T_, 256>>>((const float*)pXT, (const float*)pYP, (__half*)pZh);
    // out = Zh @ Wh^T + b_cls  (persistent)
    {
        cudaFuncSetAttribute(joint_gemm_f16, cudaFuncAttributeMaxDynamicSharedMemorySize,
                             JSMEM);
        joint_gemm_f16<<<NJCTAS, 128, JSMEM>>>((const __half*)pZh, (const __half*)pWh,
                                               b_cls, out);
    }
}

// round 10
// speedup vs baseline: 2.3145x; 1.0107x over previous
#include <cuda_runtime.h>
#include <cuda_fp16.h>
#include <cstdint>

// ---------------------------------------------------------------------------
// RNN-T joint network (sm_103 legacy tensor path, fp16 mma):
//   XT = x@W_tr + b_tr            [1600, 256]  fp32
//   YP = y@W_pr + b_pr            [400, 256]   fp32
//   Zh = fp16(tanh(XT[bt] + YP[b,u]))  [160000, 256]
//   out= Zh @ Wh + b_cls          [160000, 1024]  mma.sync m16n8k16 f16,f32acc
// Joint GEMM: persistent CTAs (296 = 2/SM), B resident in smem, A streamed
// via continuous 3-stage cp.async ring, bias in registers. ~90% of legacy
// fp16-HMMA pipe rate. z_tanh: 4 cols/thread, float4 loads, STG.64 stores.
// ---------------------------------------------------------------------------

#define B_  4
#define T_  400
#define U_  100
#define DTR 768
#define DPR 640
#define DJ  256
#define V_  1024
#define M_TOTAL (B_ * T_ * U_)   // 160000

__device__ float  g_XT[(size_t)B_ * T_ * DJ];
__device__ float  g_YP[(size_t)B_ * U_ * DJ];
__device__ __half g_Zh[(size_t)M_TOTAL * DJ];   // 82 MB
__device__ __half g_Wh[(size_t)V_ * DJ];        // fp16(W_cls^T), n-major [V][DJ]

__device__ __forceinline__ float fast_tanh(float x) {
    float r;
    asm("tanh.approx.f32 %0, %1;" : "=f"(r) : "f"(x));
    return r;
}

__device__ __forceinline__ void mma_f16(float* c, const uint32_t* a, const uint32_t* b) {
    asm volatile(
        "mma.sync.aligned.m16n8k16.row.col.f32.f16.f16.f32 "
        "{%0,%1,%2,%3}, {%4,%5,%6,%7}, {%8,%9}, {%0,%1,%2,%3};\n"
        : "+f"(c[0]), "+f"(c[1]), "+f"(c[2]), "+f"(c[3])
        : "r"(a[0]), "r"(a[1]), "r"(a[2]), "r"(a[3]), "r"(b[0]), "r"(b[1]));
}

__device__ __forceinline__ void ldsm_x4(uint32_t& r0, uint32_t& r1, uint32_t& r2,
                                        uint32_t& r3, uint32_t addr) {
    asm volatile("ldmatrix.sync.aligned.m8n8.x4.shared.b16 {%0,%1,%2,%3}, [%4];"
                 : "=r"(r0), "=r"(r1), "=r"(r2), "=r"(r3) : "r"(addr));
}

__device__ __forceinline__ uint32_t smem_u32(const void* p) {
    uint32_t a;
    asm("{ .reg .u64 t; cvta.to.shared.u64 t, %1; cvt.u32.u64 %0, t; }" : "=r"(a) : "l"(p));
    return a;
}

// ---------------------------------------------------------------------------
// Stage 0: Wh[n][k] = fp16(W_cls[k][n])
// ---------------------------------------------------------------------------
__global__ __launch_bounds__(256)
void transpose_w(const float* __restrict__ W, __half* __restrict__ Wh) {
    __shared__ float t[32][33];
    int n0 = blockIdx.x * 32, k0 = blockIdx.y * 32;
    int tx = threadIdx.x, ty = threadIdx.y;   // (32, 8)
#pragma unroll
    for (int i = 0; i < 32; i += 8)
        t[ty + i][tx] = W[(size_t)(k0 + ty + i) * V_ + n0 + tx];
    __syncthreads();
#pragma unroll
    for (int i = 0; i < 32; i += 8)
        Wh[(size_t)(n0 + ty + i) * DJ + k0 + tx] = __float2half_rn(t[tx][ty + i]);
}

// ---------------------------------------------------------------------------
// Stage 1: small fp32 GEMM with bias, C[M,256] = A[M,K] @ W[K,256] + bias
// ---------------------------------------------------------------------------
__global__ __launch_bounds__(256)
void gemm_bias_f32(const float* __restrict__ A, const float* __restrict__ W,
                   const float* __restrict__ bias, float* __restrict__ C,
                   int M, int K) {
    const int N = DJ;
    __shared__ float As[16][68];
    __shared__ float Ws[16][68];

    int m0 = blockIdx.x * 64, n0 = blockIdx.y * 64;
    int tid = threadIdx.x;
    int ty = tid >> 4, tx = tid & 15;

    float acc[4][4];
#pragma unroll
    for (int i = 0; i < 4; i++)
#pragma unroll
        for (int j = 0; j < 4; j++) acc[i][j] = 0.f;

    for (int k0 = 0; k0 < K; k0 += 16) {
        {
            int row = tid >> 2, kc = (tid & 3) << 2;
            float4 v = make_float4(0.f, 0.f, 0.f, 0.f);
            int m = m0 + row;
            if (m < M) v = *(const float4*)(A + (size_t)m * K + k0 + kc);
            As[kc + 0][row] = v.x;
            As[kc + 1][row] = v.y;
            As[kc + 2][row] = v.z;
            As[kc + 3][row] = v.w;
        }
        {
            int kr = tid >> 4, nc = (tid & 15) << 2;
            float4 w = *(const float4*)(W + (size_t)(k0 + kr) * N + n0 + nc);
            *(float4*)&Ws[kr][nc] = w;
        }
        __syncthreads();
#pragma unroll
        for (int kk = 0; kk < 16; kk++) {
            float a[4], b[4];
#pragma unroll
            for (int i = 0; i < 4; i++) a[i] = As[kk][ty * 4 + i];
#pragma unroll
            for (int j = 0; j < 4; j++) b[j] = Ws[kk][tx * 4 + j];
#pragma unroll
            for (int i = 0; i < 4; i++)
#pragma unroll
                for (int j = 0; j < 4; j++) acc[i][j] = fmaf(a[i], b[j], acc[i][j]);
        }
        __syncthreads();
    }
#pragma unroll
    for (int i = 0; i < 4; i++) {
        int m = m0 + ty * 4 + i;
        if (m >= M) continue;
#pragma unroll
        for (int j = 0; j < 4; j++) {
            int n = n0 + tx * 4 + j;
            C[(size_t)m * N + n] = acc[i][j] + bias[n];
        }
    }
}

// ---------------------------------------------------------------------------
// Stage 2: Zh = fp16(tanh_hw(XT[bt,:] + YP[b*U+u,:]))
// Block per bt (grid 1600, block 256). XT row staged through smem once; each
// thread keeps 4 columns in registers. 4 u-phases x 64 threads cover 256 cols.
// Per 4 elems: 1 float4 LDG + 4 tanh + 2 cvt-packs + 1 STG.64.
// ---------------------------------------------------------------------------
__global__ __launch_bounds__(256)
void z_tanh_kernel(const float* __restrict__ XT, const float* __restrict__ YP,
                   __half* __restrict__ Z) {
    __shared__ float xs[DJ];
    const int bt = blockIdx.x;          // 0..1599
    const int b = bt / T_;
    const int tid = threadIdx.x;

    xs[tid] = XT[(size_t)bt * DJ + tid];
    __syncthreads();

    const int phase = tid >> 6;         // 0..3: u residue
    const int c4 = (tid & 63) * 4;      // column quad
    const float x0 = xs[c4];
    const float x1 = xs[c4 + 1];
    const float x2 = xs[c4 + 2];
    const float x3 = xs[c4 + 3];

    __half* zrow = Z + (size_t)bt * U_ * DJ + c4;
    const float* yb = YP + (size_t)b * U_ * DJ + c4;

#pragma unroll 5
    for (int u = phase; u < U_; u += 4) {
        float4 yv = *(const float4*)(yb + (size_t)u * DJ);
        __half2 h0 = __floats2half2_rn(fast_tanh(x0 + yv.x), fast_tanh(x1 + yv.y));
        __half2 h1 = __floats2half2_rn(fast_tanh(x2 + yv.z), fast_tanh(x3 + yv.w));
        uint2 pk;
        pk.x = *reinterpret_cast<uint32_t*>(&h0);
        pk.y = *reinterpret_cast<uint32_t*>(&h1);
        *reinterpret_cast<uint2*>(zrow + (size_t)u * DJ) = pk;
    }
}

// ---------------------------------------------------------------------------
// Stage 3: out = Zh @ Wh^T + b_cls, persistent CTAs.
// 296 CTAs (2/SM): CTA c -> n-tile (c&7), m-group (c>>3); loops m-tiles
// t = mgroup, mgroup+37, ...  B resident in smem (512B rows, chunk^=(row&7)).
// A: 3-stage ring of 16KB k-chunks, cp.async streamed continuously.
// Bias in registers.
// ---------------------------------------------------------------------------
#define BM 128
#define BN 128
#define BKH 64                                  // halves per A chunk
#define ROWB 128                                // A tile row bytes
#define A_STAGE_BYTES (BM * ROWB)               // 16384
#define NSTAGES 3
#define B_BYTES (BN * DJ * 2)                   // 65536
#define B_OFF (NSTAGES * A_STAGE_BYTES)         // 49152
#define JSMEM (B_OFF + B_BYTES)                 // 114688
#define NCHUNKS (DJ / BKH)                      // 4
#define MGROUPS 37
#define MTILES (M_TOTAL / BM)                   // 1250
#define NJCTAS (8 * MGROUPS)                    // 296

__global__ __launch_bounds__(128, 2)
void joint_gemm_f16(const __half* __restrict__ Z, const __half* __restrict__ Wh,
                    const float* __restrict__ bias, float* __restrict__ out) {
    extern __shared__ char sm[];
    const uint32_t smbase = smem_u32(sm);
    const uint32_t bbase = smbase + B_OFF;

    const int K = DJ;     // 256
    const int N = V_;     // 1024

    const int n0 = (blockIdx.x & 7) * BN;
    const int mgroup = blockIdx.x >> 3;         // 0..36
    const int tid = threadIdx.x;
    const int lane = tid & 31, w = tid >> 5;
    const int warpM = w & 1, warpN = w >> 1;    // 2 x 2
    const int wm0 = warpM * 64, wn0 = warpN * 64;
    const int gid = lane >> 2, tig = lane & 3;

    // ldmatrix lane mapping: matrix j = lane>>3; row-low = (j&1)*8+l8;
    // chunk low bit = j>>1; swizzle XOR value = l8.
    const int l8 = lane & 7, j = lane >> 3;
    const uint32_t rowlow = (uint32_t)(((j & 1) << 3) + l8);
    const uint32_t cbit = (uint32_t)(j >> 1);
    const uint32_t xorv = (uint32_t)l8;
    const uint32_t aRow = ((uint32_t)wm0 + rowlow) * ROWB;          // + fm*16*ROWB
    const uint32_t bRow = bbase + ((uint32_t)wn0 + rowlow) * 512;   // + p*16*512

    // bias hoist: the only 16 bias values this thread ever uses
    float bv[8][2];
#pragma unroll
    for (int fn = 0; fn < 8; fn++) {
        int cidx = n0 + wn0 + fn * 8 + 2 * tig;
        bv[fn][0] = bias[cidx];
        bv[fn][1] = bias[cidx + 1];
    }

    // ------- one-time B load: rows = n, 512B each, swizzled 16B chunks -------
    {
        int r = tid;                    // 0..127 (n-row)
        const __half* src = Wh + (size_t)(n0 + r) * K;
        uint32_t dbase = bbase + (uint32_t)r * 512;
        uint32_t rx = (uint32_t)(r & 7);
#pragma unroll
        for (int ch = 0; ch < 32; ch++) {
            uint32_t d = dbase + (((uint32_t)ch ^ rx) << 4);
            asm volatile("cp.async.cg.shared.global [%0], [%1], 16;"
                         :: "r"(d), "l"(src + ch * 8));
        }
        asm volatile("cp.async.commit_group;" ::: "memory");
    }

    // ------- A streaming: 128 rows x 128B per chunk -------
    const int lrow = tid >> 3;     // 0..15
    const int lchunk = tid & 7;    // 16B chunk within 128B row

#define LOAD_A(mt, c, s) do { \
    uint32_t _sb = smbase + (uint32_t)(s) * A_STAGE_BYTES; \
    _Pragma("unroll") \
    for (int p = 0; p < 8; p++) { \
        int _r = lrow + p * 16; \
        uint32_t _d = _sb + (uint32_t)_r * ROWB + \
                      ((uint32_t)(lchunk ^ (_r & 7)) << 4); \
        const __half* _a = Z + (size_t)((mt) * BM + _r) * K + (c) * BKH + lchunk * 8; \
        asm volatile("cp.async.cg.shared.global [%0], [%1], 16;" \
                     :: "r"(_d), "l"(_a)); \
    } \
    asm volatile("cp.async.commit_group;" ::: "memory"); \
} while (0)

    // load cursor
    int lt = mgroup;     // m-tile being loaded (-1 = exhausted)
    int lc = 0;          // chunk within tile
    int ls = 0;          // stage ring
#define ADV_LOAD() do { \
    if (++lc == NCHUNKS) { lc = 0; lt += MGROUPS; if (lt >= MTILES) lt = -1; } \
    ls = (ls + 1 == NSTAGES) ? 0 : ls + 1; \
} while (0)

    LOAD_A(lt, lc, ls); ADV_LOAD();
    LOAD_A(lt, lc, ls); ADV_LOAD();

    int cs = 0;          // consume stage ring

#pragma unroll 1
    for (int t = mgroup; t < MTILES; t += MGROUPS) {
        const int m0 = t * BM;
        const bool lastTile = (t + MGROUPS >= MTILES);

        float acc[4][8][4];
#pragma unroll
        for (int fm = 0; fm < 4; fm++)
#pragma unroll
            for (int fn = 0; fn < 8; fn++)
#pragma unroll
                for (int r = 0; r < 4; r++) acc[fm][fn][r] = 0.f;

#pragma unroll
        for (int c = 0; c < NCHUNKS; c++) {
            if (lastTile && c == NCHUNKS - 1)
                asm volatile("cp.async.wait_group 0;" ::: "memory");
            else
                asm volatile("cp.async.wait_group 1;" ::: "memory");
            __syncthreads();
            if (lt >= 0) { LOAD_A(lt, lc, ls); ADV_LOAD(); }

            const uint32_t aB = smbase + (uint32_t)cs * A_STAGE_BYTES + aRow;
            cs = (cs + 1 == NSTAGES) ? 0 : cs + 1;
#pragma unroll
            for (int ks = 0; ks < 4; ks++) {              // 4 x k16 per chunk
                const uint32_t aCh = (((uint32_t)(ks << 1) + cbit) ^ xorv) << 4;
                const uint32_t bCh = (((uint32_t)(c * 8 + (ks << 1)) + cbit) ^ xorv) << 4;
                uint32_t a[4][4], b[8][2];
#pragma unroll
                for (int fm = 0; fm < 4; fm++)
                    ldsm_x4(a[fm][0], a[fm][1], a[fm][2], a[fm][3],
                            aB + (uint32_t)fm * (16 * ROWB) + aCh);
#pragma unroll
                for (int p = 0; p < 4; p++) {
                    uint32_t r0, r1, r2, r3;
                    ldsm_x4(r0, r1, r2, r3, bRow + (uint32_t)p * (16 * 512) + bCh);
                    b[2 * p][0] = r0;
                    b[2 * p + 1][0] = r1;
                    b[2 * p][1] = r2;
                    b[2 * p + 1][1] = r3;
                }
#pragma unroll
                for (int fm = 0; fm < 4; fm++)
#pragma unroll
                    for (int fn = 0; fn < 8; fn++) mma_f16(acc[fm][fn], a[fm], b[fn]);
            }
        }

        // epilogue: bias (registers) + store
#pragma unroll
        for (int fm = 0; fm < 4; fm++) {
            int r0 = m0 + wm0 + fm * 16 + gid;
#pragma unroll
            for (int fn = 0; fn < 8; fn++) {
                int cidx = n0 + wn0 + fn * 8 + 2 * tig;
                float2 v0 = make_float2(acc[fm][fn][0] + bv[fn][0],
                                        acc[fm][fn][1] + bv[fn][1]);
                float2 v1 = make_float2(acc[fm][fn][2] + bv[fn][0],
                                        acc[fm][fn][3] + bv[fn][1]);
                *(float2*)(out + (size_t)r0 * N + cidx) = v0;
                *(float2*)(out + (size_t)(r0 + 8) * N + cidx) = v1;
            }
        }
    }
#undef LOAD_A
#undef ADV_LOAD
}

// ---------------------------------------------------------------------------
extern "C" void kernel_launch(void* const* d_in, const int* in_sizes, int n_in,
                              void* d_out, int out_size) {
    const float* x     = (const float*)d_in[0];
    const float* y     = (const float*)d_in[1];
    const float* W_tr  = (const float*)d_in[2];
    const float* b_tr  = (const float*)d_in[3];
    const float* W_pr  = (const float*)d_in[4];
    const float* b_pr  = (const float*)d_in[5];
    const float* W_cls = (const float*)d_in[6];
    const float* b_cls = (const float*)d_in[7];
    float* out = (float*)d_out;

    void *pXT, *pYP, *pZh, *pWh;
    cudaGetSymbolAddress(&pXT, g_XT);
    cudaGetSymbolAddress(&pYP, g_YP);
    cudaGetSymbolAddress(&pZh, g_Zh);
    cudaGetSymbolAddress(&pWh, g_Wh);

    // Wh = fp16(W_cls^T)
    {
        dim3 grid(V_ / 32, DJ / 32);
        transpose_w<<<grid, dim3(32, 8)>>>(W_cls, (__half*)pWh);
    }
    // XT = x @ W_tr + b_tr
    {
        dim3 grid((B_ * T_ + 63) / 64, DJ / 64);
        gemm_bias_f32<<<grid, 256>>>(x, W_tr, b_tr, (float*)pXT, B_ * T_, DTR);
    }
    // YP = y @ W_pr + b_pr
    {
        dim3 grid((B_ * U_ + 63) / 64, DJ / 64);
        gemm_bias_f32<<<grid, 256>>>(y, W_pr, b_pr, (float*)pYP, B_ * U_, DPR);
    }
    // Zh = fp16(tanh(XT + YP))
    z_tanh_kernel<<<B_ * T_, 256>>>((const float*)pXT, (const float*)pYP, (__half*)pZh);
    // out = Zh @ Wh^T + b_cls  (persistent)
    {
        cudaFuncSetAttribute(joint_gemm_f16, cudaFuncAttributeMaxDynamicSharedMemorySize,
                             JSMEM);
        joint_gemm_f16<<<NJCTAS, 128, JSMEM>>>((const __half*)pZh, (const __half*)pWh,
                                               b_cls, out);
    }
}

// round 11
// speedup vs baseline: 2.8223x; 1.2194x over previous
#include <cuda_runtime.h>
#include <cuda_fp16.h>
#include <cstdint>

// ---------------------------------------------------------------------------
// RNN-T joint network (sm_103 legacy tensor path, fp16 mma everywhere):
//   XT = x@W_tr + b_tr   [1600,256] fp32 out, fp16 tensor math
//   YP = y@W_pr + b_pr   [400,256]  fp32 out, fp16 tensor math
//   Zh = fp16(tanh(XT[bt] + YP[b,u]))  [160000, 256]
//   out= Zh @ Wh + b_cls [160000,1024]  persistent fp16 mma (pipe-bound)
// ---------------------------------------------------------------------------

#define B_  4
#define T_  400
#define U_  100
#define DTR 768
#define DPR 640
#define DJ  256
#define V_  1024
#define M_TOTAL (B_ * T_ * U_)   // 160000

__device__ float  g_XT[(size_t)B_ * T_ * DJ];
__device__ float  g_YP[(size_t)B_ * U_ * DJ];
__device__ __half g_Zh[(size_t)M_TOTAL * DJ];    // 82 MB
__device__ __half g_Wh[(size_t)V_ * DJ];         // fp16(W_cls^T)  [V][DJ]
__device__ __half g_WtrT[(size_t)DJ * DTR];      // fp16(W_tr^T)   [256][768]
__device__ __half g_WprT[(size_t)DJ * DPR];      // fp16(W_pr^T)   [256][640]

__device__ __forceinline__ float fast_tanh(float x) {
    float r;
    asm("tanh.approx.f32 %0, %1;" : "=f"(r) : "f"(x));
    return r;
}

__device__ __forceinline__ void mma_f16(float* c, const uint32_t* a, const uint32_t* b) {
    asm volatile(
        "mma.sync.aligned.m16n8k16.row.col.f32.f16.f16.f32 "
        "{%0,%1,%2,%3}, {%4,%5,%6,%7}, {%8,%9}, {%0,%1,%2,%3};\n"
        : "+f"(c[0]), "+f"(c[1]), "+f"(c[2]), "+f"(c[3])
        : "r"(a[0]), "r"(a[1]), "r"(a[2]), "r"(a[3]), "r"(b[0]), "r"(b[1]));
}

__device__ __forceinline__ void ldsm_x4(uint32_t& r0, uint32_t& r1, uint32_t& r2,
                                        uint32_t& r3, uint32_t addr) {
    asm volatile("ldmatrix.sync.aligned.m8n8.x4.shared.b16 {%0,%1,%2,%3}, [%4];"
                 : "=r"(r0), "=r"(r1), "=r"(r2), "=r"(r3) : "r"(addr));
}

__device__ __forceinline__ uint32_t smem_u32(const void* p) {
    uint32_t a;
    asm("{ .reg .u64 t; cvta.to.shared.u64 t, %1; cvt.u32.u64 %0, t; }" : "=r"(a) : "l"(p));
    return a;
}

// ---------------------------------------------------------------------------
// Stage 0a: Wh[n][k] = fp16(W_cls[k][n])   (src N = V_)
// ---------------------------------------------------------------------------
__global__ __launch_bounds__(256)
void transpose_w(const float* __restrict__ W, __half* __restrict__ Wh) {
    __shared__ float t[32][33];
    int n0 = blockIdx.x * 32, k0 = blockIdx.y * 32;
    int tx = threadIdx.x, ty = threadIdx.y;   // (32, 8)
#pragma unroll
    for (int i = 0; i < 32; i += 8)
        t[ty + i][tx] = W[(size_t)(k0 + ty + i) * V_ + n0 + tx];
    __syncthreads();
#pragma unroll
    for (int i = 0; i < 32; i += 8)
        Wh[(size_t)(n0 + ty + i) * DJ + k0 + tx] = __float2half_rn(t[tx][ty + i]);
}

// ---------------------------------------------------------------------------
// Stage 0b: Wt[n][k] = fp16(W[k][n]) for [K,256] fp32 weights (K param)
// ---------------------------------------------------------------------------
__global__ __launch_bounds__(256)
void transpose_wk(const float* __restrict__ W, __half* __restrict__ Wt, int K) {
    __shared__ float t[32][33];
    int n0 = blockIdx.x * 32, k0 = blockIdx.y * 32;
    int tx = threadIdx.x, ty = threadIdx.y;   // (32, 8)
#pragma unroll
    for (int i = 0; i < 32; i += 8)
        t[ty + i][tx] = W[(size_t)(k0 + ty + i) * DJ + n0 + tx];
    __syncthreads();
#pragma unroll
    for (int i = 0; i < 32; i += 8)
        Wt[(size_t)(n0 + ty + i) * K + k0 + tx] = __float2half_rn(t[tx][ty + i]);
}

// ---------------------------------------------------------------------------
// Stage 1 (fused XT + YP): fp16 tensor GEMM, fp32-out.
// 125 blocks x 16 m-rows: blk 0..99 -> XT (A=x, K=768), 100..124 -> YP.
// Block 256 thr = 8 warps; warp w covers n columns [32w, 32w+32).
// B chunks [256n][64k] fp16 (128B rows, chunk^=(row&7)) double-buffered
// via cp.async; A chunk [16m][64k] converted fp32->fp16 inline into smem.
// Fragment addressing identical to the (verified) joint kernel.
// ---------------------------------------------------------------------------
#define IG_B_STAGE 32768                     // 256 * 128
#define IG_A_STAGE 2048                      // 16 * 128
#define IG_SMEM (2 * IG_B_STAGE + 2 * IG_A_STAGE)   // 69632

__global__ __launch_bounds__(256)
void in_gemm_f16(const float* __restrict__ x, const float* __restrict__ y,
                 const __half* __restrict__ WtrT, const __half* __restrict__ WprT,
                 const float* __restrict__ btr, const float* __restrict__ bpr,
                 float* __restrict__ XT, float* __restrict__ YP) {
    extern __shared__ char sm[];
    const uint32_t smbase = smem_u32(sm);
    const uint32_t abase = smbase + 2 * IG_B_STAGE;

    const int blk = blockIdx.x;
    const bool isY = blk >= 100;
    const float* A = isY ? y : x;
    const __half* Wt = isY ? WprT : WtrT;
    const float* bias = isY ? bpr : btr;
    float* C = isY ? YP : XT;
    const int m0 = (isY ? blk - 100 : blk) * 16;
    const int K = isY ? DPR : DTR;
    const int nch = K / 64;                  // 10 or 12

    const int tid = threadIdx.x;
    const int lane = tid & 31, w = tid >> 5;
    const int wn0 = w * 32;
    const int gid = lane >> 2, tig = lane & 3;

    const int l8 = lane & 7, j = lane >> 3;
    const uint32_t rowlow = (uint32_t)(((j & 1) << 3) + l8);
    const uint32_t cbit = (uint32_t)(j >> 1);
    const uint32_t xorv = (uint32_t)l8;

    // A store mapping: thread t -> row t>>4, col-quad t&15 (4 floats -> 8B)
    const int a_row = tid >> 4;
    const int a_cq = tid & 15;
    const float* a_src = A + (size_t)(m0 + a_row) * K + a_cq * 4;
    const uint32_t a_dst = abase + (uint32_t)a_row * 128 +
                           (((uint32_t)(a_cq >> 1) ^ (uint32_t)(a_row & 7)) << 4) +
                           (uint32_t)(a_cq & 1) * 8;

    // B load mapping: thread t -> row t, 8 x 16B chunks
    const __half* b_src = Wt + (size_t)tid * K;
    const uint32_t b_dst = smbase + (uint32_t)tid * 128;
    const uint32_t brx = (uint32_t)(tid & 7);

#define IG_LOAD_B(c, s) do { \
    uint32_t _d = b_dst + (uint32_t)(s) * IG_B_STAGE; \
    const __half* _s = b_src + (c) * 64; \
    _Pragma("unroll") \
    for (int ch = 0; ch < 8; ch++) \
        asm volatile("cp.async.cg.shared.global [%0], [%1], 16;" \
                     :: "r"(_d + (((uint32_t)ch ^ brx) << 4)), "l"(_s + ch * 8)); \
    asm volatile("cp.async.commit_group;" ::: "memory"); \
} while (0)

    float acc[4][4];
#pragma unroll
    for (int fn = 0; fn < 4; fn++)
#pragma unroll
        for (int r = 0; r < 4; r++) acc[fn][r] = 0.f;

    IG_LOAD_B(0, 0);

#pragma unroll 1
    for (int c = 0; c < nch; c++) {
        const int s = c & 1;
        // A(c): fp32 load + cvt + 8B smem store
        {
            float4 v = *(const float4*)(a_src + c * 64);
            __half2 h0 = __floats2half2_rn(v.x, v.y);
            __half2 h1 = __floats2half2_rn(v.z, v.w);
            uint2 pk;
            pk.x = *reinterpret_cast<uint32_t*>(&h0);
            pk.y = *reinterpret_cast<uint32_t*>(&h1);
            *reinterpret_cast<uint2*>(
                reinterpret_cast<char*>(sm) + (a_dst - smbase) + s * IG_A_STAGE) = pk;
        }
        if (c + 1 < nch) {
            IG_LOAD_B(c + 1, (c + 1) & 1);
            asm volatile("cp.async.wait_group 1;" ::: "memory");
        } else {
            asm volatile("cp.async.wait_group 0;" ::: "memory");
        }
        __syncthreads();

        const uint32_t aB = abase + (uint32_t)s * IG_A_STAGE + rowlow * 128;
        const uint32_t bB = smbase + (uint32_t)s * IG_B_STAGE +
                            ((uint32_t)wn0 + rowlow) * 128;
#pragma unroll
        for (int ks = 0; ks < 4; ks++) {
            const uint32_t ch = (((uint32_t)(ks << 1) + cbit) ^ xorv) << 4;
            uint32_t a[4], b[4][2];
            ldsm_x4(a[0], a[1], a[2], a[3], aB + ch);
#pragma unroll
            for (int p = 0; p < 2; p++) {
                uint32_t r0, r1, r2, r3;
                ldsm_x4(r0, r1, r2, r3, bB + (uint32_t)p * (16 * 128) + ch);
                b[2 * p][0] = r0;
                b[2 * p + 1][0] = r1;
                b[2 * p][1] = r2;
                b[2 * p + 1][1] = r3;
            }
#pragma unroll
            for (int fn = 0; fn < 4; fn++) mma_f16(acc[fn], a, b[fn]);
        }
        __syncthreads();
    }
#undef IG_LOAD_B

    // epilogue: bias + fp32 store
#pragma unroll
    for (int fn = 0; fn < 4; fn++) {
        int cidx = wn0 + fn * 8 + 2 * tig;
        float bv0 = __ldg(bias + cidx);
        float bv1 = __ldg(bias + cidx + 1);
        float* r0p = C + (size_t)(m0 + gid) * DJ + cidx;
        float* r1p = C + (size_t)(m0 + gid + 8) * DJ + cidx;
        r0p[0] = acc[fn][0] + bv0;
        r0p[1] = acc[fn][1] + bv1;
        r1p[0] = acc[fn][2] + bv0;
        r1p[1] = acc[fn][3] + bv1;
    }
}

// ---------------------------------------------------------------------------
// Stage 2: Zh = fp16(tanh_hw(XT[bt,:] + YP[b*U+u,:]))
// Block per bt. Direct float4 loads (L1-hot), 4 cols/thread, STG.64 stores.
// ---------------------------------------------------------------------------
__global__ __launch_bounds__(256)
void z_tanh_kernel(const float* __restrict__ XT, const float* __restrict__ YP,
                   __half* __restrict__ Z) {
    const int bt = blockIdx.x;          // 0..1599
    const int b = bt / T_;
    const int tid = threadIdx.x;

    const int phase = tid >> 6;         // 0..3: u residue
    const int c4 = (tid & 63) * 4;      // column quad
    float4 xv = *(const float4*)(XT + (size_t)bt * DJ + c4);

    __half* zrow = Z + (size_t)bt * U_ * DJ + c4;
    const float* yb = YP + (size_t)b * U_ * DJ + c4;

#pragma unroll 5
    for (int u = phase; u < U_; u += 4) {
        float4 yv = *(const float4*)(yb + (size_t)u * DJ);
        __half2 h0 = __floats2half2_rn(fast_tanh(xv.x + yv.x), fast_tanh(xv.y + yv.y));
        __half2 h1 = __floats2half2_rn(fast_tanh(xv.z + yv.z), fast_tanh(xv.w + yv.w));
        uint2 pk;
        pk.x = *reinterpret_cast<uint32_t*>(&h0);
        pk.y = *reinterpret_cast<uint32_t*>(&h1);
        *reinterpret_cast<uint2*>(zrow + (size_t)u * DJ) = pk;
    }
}

// ---------------------------------------------------------------------------
// Stage 3: out = Zh @ Wh^T + b_cls, persistent CTAs (unchanged from R10).
// ---------------------------------------------------------------------------
#define BM 128
#define BN 128
#define BKH 64
#define ROWB 128
#define A_STAGE_BYTES (BM * ROWB)               // 16384
#define NSTAGES 3
#define B_BYTES (BN * DJ * 2)                   // 65536
#define B_OFF (NSTAGES * A_STAGE_BYTES)         // 49152
#define JSMEM (B_OFF + B_BYTES)                 // 114688
#define NCHUNKS (DJ / BKH)                      // 4
#define MGROUPS 37
#define MTILES (M_TOTAL / BM)                   // 1250
#define NJCTAS (8 * MGROUPS)                    // 296

__global__ __launch_bounds__(128, 2)
void joint_gemm_f16(const __half* __restrict__ Z, const __half* __restrict__ Wh,
                    const float* __restrict__ bias, float* __restrict__ out) {
    extern __shared__ char sm[];
    const uint32_t smbase = smem_u32(sm);
    const uint32_t bbase = smbase + B_OFF;

    const int K = DJ;
    const int N = V_;

    const int n0 = (blockIdx.x & 7) * BN;
    const int mgroup = blockIdx.x >> 3;
    const int tid = threadIdx.x;
    const int lane = tid & 31, w = tid >> 5;
    const int warpM = w & 1, warpN = w >> 1;
    const int wm0 = warpM * 64, wn0 = warpN * 64;
    const int gid = lane >> 2, tig = lane & 3;

    const int l8 = lane & 7, j = lane >> 3;
    const uint32_t rowlow = (uint32_t)(((j & 1) << 3) + l8);
    const uint32_t cbit = (uint32_t)(j >> 1);
    const uint32_t xorv = (uint32_t)l8;
    const uint32_t aRow = ((uint32_t)wm0 + rowlow) * ROWB;
    const uint32_t bRow = bbase + ((uint32_t)wn0 + rowlow) * 512;

    float bv[8][2];
#pragma unroll
    for (int fn = 0; fn < 8; fn++) {
        int cidx = n0 + wn0 + fn * 8 + 2 * tig;
        bv[fn][0] = bias[cidx];
        bv[fn][1] = bias[cidx + 1];
    }

    {
        int r = tid;
        const __half* src = Wh + (size_t)(n0 + r) * K;
        uint32_t dbase = bbase + (uint32_t)r * 512;
        uint32_t rx = (uint32_t)(r & 7);
#pragma unroll
        for (int ch = 0; ch < 32; ch++) {
            uint32_t d = dbase + (((uint32_t)ch ^ rx) << 4);
            asm volatile("cp.async.cg.shared.global [%0], [%1], 16;"
                         :: "r"(d), "l"(src + ch * 8));
        }
        asm volatile("cp.async.commit_group;" ::: "memory");
    }

    const int lrow = tid >> 3;
    const int lchunk = tid & 7;

#define LOAD_A(mt, c, s) do { \
    uint32_t _sb = smbase + (uint32_t)(s) * A_STAGE_BYTES; \
    _Pragma("unroll") \
    for (int p = 0; p < 8; p++) { \
        int _r = lrow + p * 16; \
        uint32_t _d = _sb + (uint32_t)_r * ROWB + \
                      ((uint32_t)(lchunk ^ (_r & 7)) << 4); \
        const __half* _a = Z + (size_t)((mt) * BM + _r) * K + (c) * BKH + lchunk * 8; \
        asm volatile("cp.async.cg.shared.global [%0], [%1], 16;" \
                     :: "r"(_d), "l"(_a)); \
    } \
    asm volatile("cp.async.commit_group;" ::: "memory"); \
} while (0)

    int lt = mgroup;
    int lc = 0;
    int ls = 0;
#define ADV_LOAD() do { \
    if (++lc == NCHUNKS) { lc = 0; lt += MGROUPS; if (lt >= MTILES) lt = -1; } \
    ls = (ls + 1 == NSTAGES) ? 0 : ls + 1; \
} while (0)

    LOAD_A(lt, lc, ls); ADV_LOAD();
    LOAD_A(lt, lc, ls); ADV_LOAD();

    int cs = 0;

#pragma unroll 1
    for (int t = mgroup; t < MTILES; t += MGROUPS) {
        const int m0 = t * BM;
        const bool lastTile = (t + MGROUPS >= MTILES);

        float acc[4][8][4];
#pragma unroll
        for (int fm = 0; fm < 4; fm++)
#pragma unroll
            for (int fn = 0; fn < 8; fn++)
#pragma unroll
                for (int r = 0; r < 4; r++) acc[fm][fn][r] = 0.f;

#pragma unroll
        for (int c = 0; c < NCHUNKS; c++) {
            if (lastTile && c == NCHUNKS - 1)
                asm volatile("cp.async.wait_group 0;" ::: "memory");
            else
                asm volatile("cp.async.wait_group 1;" ::: "memory");
            __syncthreads();
            if (lt >= 0) { LOAD_A(lt, lc, ls); ADV_LOAD(); }

            const uint32_t aB = smbase + (uint32_t)cs * A_STAGE_BYTES + aRow;
            cs = (cs + 1 == NSTAGES) ? 0 : cs + 1;
#pragma unroll
            for (int ks = 0; ks < 4; ks++) {
                const uint32_t aCh = (((uint32_t)(ks << 1) + cbit) ^ xorv) << 4;
                const uint32_t bCh = (((uint32_t)(c * 8 + (ks << 1)) + cbit) ^ xorv) << 4;
                uint32_t a[4][4], b[8][2];
#pragma unroll
                for (int fm = 0; fm < 4; fm++)
                    ldsm_x4(a[fm][0], a[fm][1], a[fm][2], a[fm][3],
                            aB + (uint32_t)fm * (16 * ROWB) + aCh);
#pragma unroll
                for (int p = 0; p < 4; p++) {
                    uint32_t r0, r1, r2, r3;
                    ldsm_x4(r0, r1, r2, r3, bRow + (uint32_t)p * (16 * 512) + bCh);
                    b[2 * p][0] = r0;
                    b[2 * p + 1][0] = r1;
                    b[2 * p][1] = r2;
                    b[2 * p + 1][1] = r3;
                }
#pragma unroll
                for (int fm = 0; fm < 4; fm++)
#pragma unroll
                    for (int fn = 0; fn < 8; fn++) mma_f16(acc[fm][fn], a[fm], b[fn]);
            }
        }

#pragma unroll
        for (int fm = 0; fm < 4; fm++) {
            int r0 = m0 + wm0 + fm * 16 + gid;
#pragma unroll
            for (int fn = 0; fn < 8; fn++) {
                int cidx = n0 + wn0 + fn * 8 + 2 * tig;
                float2 v0 = make_float2(acc[fm][fn][0] + bv[fn][0],
                                        acc[fm][fn][1] + bv[fn][1]);
                float2 v1 = make_float2(acc[fm][fn][2] + bv[fn][0],
                                        acc[fm][fn][3] + bv[fn][1]);
                *(float2*)(out + (size_t)r0 * N + cidx) = v0;
                *(float2*)(out + (size_t)(r0 + 8) * N + cidx) = v1;
            }
        }
    }
#undef LOAD_A
#undef ADV_LOAD
}

// ---------------------------------------------------------------------------
extern "C" void kernel_launch(void* const* d_in, const int* in_sizes, int n_in,
                              void* d_out, int out_size) {
    const float* x     = (const float*)d_in[0];
    const float* y     = (const float*)d_in[1];
    const float* W_tr  = (const float*)d_in[2];
    const float* b_tr  = (const float*)d_in[3];
    const float* W_pr  = (const float*)d_in[4];
    const float* b_pr  = (const float*)d_in[5];
    const float* W_cls = (const float*)d_in[6];
    const float* b_cls = (const float*)d_in[7];
    float* out = (float*)d_out;

    void *pXT, *pYP, *pZh, *pWh, *pWtrT, *pWprT;
    cudaGetSymbolAddress(&pXT, g_XT);
    cudaGetSymbolAddress(&pYP, g_YP);
    cudaGetSymbolAddress(&pZh, g_Zh);
    cudaGetSymbolAddress(&pWh, g_Wh);
    cudaGetSymbolAddress(&pWtrT, g_WtrT);
    cudaGetSymbolAddress(&pWprT, g_WprT);

    // weight preps
    {
        dim3 grid(V_ / 32, DJ / 32);
        transpose_w<<<grid, dim3(32, 8)>>>(W_cls, (__half*)pWh);
    }
    transpose_wk<<<dim3(DJ / 32, DTR / 32), dim3(32, 8)>>>(W_tr, (__half*)pWtrT, DTR);
    transpose_wk<<<dim3(DJ / 32, DPR / 32), dim3(32, 8)>>>(W_pr, (__half*)pWprT, DPR);

    // stage 1: XT and YP (fused, fp16 tensor)
    {
        cudaFuncSetAttribute(in_gemm_f16, cudaFuncAttributeMaxDynamicSharedMemorySize,
                             IG_SMEM);
        in_gemm_f16<<<125, 256, IG_SMEM>>>(x, y, (const __half*)pWtrT,
                                           (const __half*)pWprT, b_tr, b_pr,
                                           (float*)pXT, (float*)pYP);
    }
    // stage 2
    z_tanh_kernel<<<B_ * T_, 256>>>((const float*)pXT, (const float*)pYP, (__half*)pZh);
    // stage 3 (persistent)
    {
        cudaFuncSetAttribute(joint_gemm_f16, cudaFuncAttributeMaxDynamicSharedMemorySize,
                             JSMEM);
        joint_gemm_f16<<<NJCTAS, 128, JSMEM>>>((const __half*)pZh, (const __half*)pWh,
                                               b_cls, out);
    }
}

// round 12
// speedup vs baseline: 2.8653x; 1.0152x over previous
#include <cuda_runtime.h>
#include <cuda_fp16.h>
#include <cstdint>

// ---------------------------------------------------------------------------
// RNN-T joint network (sm_103 legacy tensor path, fp16 mma everywhere):
//   XT = x@W_tr + b_tr   [1600,256] fp32 out, fp16 tensor math
//   YP = y@W_pr + b_pr   [400,256]  fp32 out, fp16 tensor math
//   Zh = fp16(tanh(XT[bt] + YP[b,u]))  [160000, 256]
//   out= Zh @ Wh + b_cls [160000,1024]  persistent fp16 mma (pipe-bound)
// ---------------------------------------------------------------------------

#define B_  4
#define T_  400
#define U_  100
#define DTR 768
#define DPR 640
#define DJ  256
#define V_  1024
#define M_TOTAL (B_ * T_ * U_)   // 160000

__device__ float  g_XT[(size_t)B_ * T_ * DJ];
__device__ float  g_YP[(size_t)B_ * U_ * DJ];
__device__ __half g_Zh[(size_t)M_TOTAL * DJ];    // 82 MB
__device__ __half g_Wh[(size_t)V_ * DJ];         // fp16(W_cls^T)  [V][DJ]
__device__ __half g_WtrT[(size_t)DJ * DTR];      // fp16(W_tr^T)   [256][768]
__device__ __half g_WprT[(size_t)DJ * DPR];      // fp16(W_pr^T)   [256][640]

__device__ __forceinline__ float fast_tanh(float x) {
    float r;
    asm("tanh.approx.f32 %0, %1;" : "=f"(r) : "f"(x));
    return r;
}

__device__ __forceinline__ void mma_f16(float* c, const uint32_t* a, const uint32_t* b) {
    asm volatile(
        "mma.sync.aligned.m16n8k16.row.col.f32.f16.f16.f32 "
        "{%0,%1,%2,%3}, {%4,%5,%6,%7}, {%8,%9}, {%0,%1,%2,%3};\n"
        : "+f"(c[0]), "+f"(c[1]), "+f"(c[2]), "+f"(c[3])
        : "r"(a[0]), "r"(a[1]), "r"(a[2]), "r"(a[3]), "r"(b[0]), "r"(b[1]));
}

__device__ __forceinline__ void ldsm_x4(uint32_t& r0, uint32_t& r1, uint32_t& r2,
                                        uint32_t& r3, uint32_t addr) {
    asm volatile("ldmatrix.sync.aligned.m8n8.x4.shared.b16 {%0,%1,%2,%3}, [%4];"
                 : "=r"(r0), "=r"(r1), "=r"(r2), "=r"(r3) : "r"(addr));
}

__device__ __forceinline__ uint32_t smem_u32(const void* p) {
    uint32_t a;
    asm("{ .reg .u64 t; cvta.to.shared.u64 t, %1; cvt.u32.u64 %0, t; }" : "=r"(a) : "l"(p));
    return a;
}

// ---------------------------------------------------------------------------
// Stage 0a: Wh[n][k] = fp16(W_cls[k][n])   (src N = V_)
// ---------------------------------------------------------------------------
__global__ __launch_bounds__(256)
void transpose_w(const float* __restrict__ W, __half* __restrict__ Wh) {
    __shared__ float t[32][33];
    int n0 = blockIdx.x * 32, k0 = blockIdx.y * 32;
    int tx = threadIdx.x, ty = threadIdx.y;   // (32, 8)
#pragma unroll
    for (int i = 0; i < 32; i += 8)
        t[ty + i][tx] = W[(size_t)(k0 + ty + i) * V_ + n0 + tx];
    __syncthreads();
#pragma unroll
    for (int i = 0; i < 32; i += 8)
        Wh[(size_t)(n0 + ty + i) * DJ + k0 + tx] = __float2half_rn(t[tx][ty + i]);
}

// ---------------------------------------------------------------------------
// Stage 0b: Wt[n][k] = fp16(W[k][n]) for [K,256] fp32 weights (K param)
// ---------------------------------------------------------------------------
__global__ __launch_bounds__(256)
void transpose_wk(const float* __restrict__ W, __half* __restrict__ Wt, int K) {
    __shared__ float t[32][33];
    int n0 = blockIdx.x * 32, k0 = blockIdx.y * 32;
    int tx = threadIdx.x, ty = threadIdx.y;   // (32, 8)
#pragma unroll
    for (int i = 0; i < 32; i += 8)
        t[ty + i][tx] = W[(size_t)(k0 + ty + i) * DJ + n0 + tx];
    __syncthreads();
#pragma unroll
    for (int i = 0; i < 32; i += 8)
        Wt[(size_t)(n0 + ty + i) * K + k0 + tx] = __float2half_rn(t[tx][ty + i]);
}

// ---------------------------------------------------------------------------
// Stage 1 v2 (fused XT + YP): fp16 tensor GEMM, fp32-out.
// Tile 16m x 64n, 128 threads (4 warps x 16n). Grid 500:
//   blk 0..399:   XT  mt = blk>>2, n-slice = blk&3  (K = 768)
//   blk 400..499: YP  mt = (blk-400)>>2, n-slice = (blk-400)&3  (K = 640)
// B [64n][64k] chunks double-buffered via cp.async (8KB each); A [16m][64k]
// converted fp32->fp16 inline into smem (2KB, double-buffered). 20KB smem ->
// high occupancy; ~3.4 CTAs/SM hides chunk latency.
// Same chunk/ks accumulation order as v1 -> bitwise-identical results.
// ---------------------------------------------------------------------------
#define IG_B_STAGE 8192                      // 64 * 128
#define IG_A_STAGE 2048                      // 16 * 128
#define IG_SMEM (2 * IG_B_STAGE + 2 * IG_A_STAGE)   // 20480

__global__ __launch_bounds__(128)
void in_gemm_f16(const float* __restrict__ x, const float* __restrict__ y,
                 const __half* __restrict__ WtrT, const __half* __restrict__ WprT,
                 const float* __restrict__ btr, const float* __restrict__ bpr,
                 float* __restrict__ XT, float* __restrict__ YP) {
    extern __shared__ char sm[];
    const uint32_t smbase = smem_u32(sm);
    const uint32_t abase = smbase + 2 * IG_B_STAGE;

    const int blk = blockIdx.x;
    const bool isY = blk >= 400;
    const int bidx = isY ? blk - 400 : blk;
    const float* A = isY ? y : x;
    const __half* Wt = isY ? WprT : WtrT;
    const float* bias = isY ? bpr : btr;
    float* C = isY ? YP : XT;
    const int m0 = (bidx >> 2) * 16;
    const int n0 = (bidx & 3) * 64;
    const int K = isY ? DPR : DTR;
    const int nch = K / 64;                  // 12 or 10

    const int tid = threadIdx.x;
    const int lane = tid & 31, w = tid >> 5;
    const int wn0 = w * 16;                  // warp n offset within 64
    const int gid = lane >> 2, tig = lane & 3;

    const int l8 = lane & 7, j = lane >> 3;
    const uint32_t rowlow = (uint32_t)(((j & 1) << 3) + l8);
    const uint32_t cbit = (uint32_t)(j >> 1);
    const uint32_t xorv = (uint32_t)l8;

    // A store: thread t -> row t>>3, 16B chunk t&7 (8 halves = 2 float4 src)
    const int a_row = tid >> 3;
    const int a_ch = tid & 7;
    const float* a_src = A + (size_t)(m0 + a_row) * K + a_ch * 8;
    const uint32_t a_dst = abase + (uint32_t)a_row * 128 +
                           (((uint32_t)a_ch ^ (uint32_t)(a_row & 7)) << 4);

    // B load: thread t -> row t>>1, 4 x 16B chunks at (t&1)*4 + i
    const int b_row = tid >> 1;
    const int b_ch0 = (tid & 1) * 4;
    const __half* b_src = Wt + (size_t)(n0 + b_row) * K + b_ch0 * 8;
    const uint32_t b_dst = smbase + (uint32_t)b_row * 128;
    const uint32_t brx = (uint32_t)(b_row & 7);

#define IG_LOAD_B(c, s) do { \
    uint32_t _d = b_dst + (uint32_t)(s) * IG_B_STAGE; \
    const __half* _s = b_src + (c) * 64; \
    _Pragma("unroll") \
    for (int i = 0; i < 4; i++) \
        asm volatile("cp.async.cg.shared.global [%0], [%1], 16;" \
                     :: "r"(_d + (((uint32_t)(b_ch0 + i) ^ brx) << 4)), "l"(_s + i * 8)); \
    asm volatile("cp.async.commit_group;" ::: "memory"); \
} while (0)

    float acc[2][4];
#pragma unroll
    for (int fn = 0; fn < 2; fn++)
#pragma unroll
        for (int r = 0; r < 4; r++) acc[fn][r] = 0.f;

    IG_LOAD_B(0, 0);

#pragma unroll 1
    for (int c = 0; c < nch; c++) {
        const int s = c & 1;
        // A(c): fp32 load + cvt + one 16B smem store
        {
            float4 v0 = *(const float4*)(a_src + c * 64);
            float4 v1 = *(const float4*)(a_src + c * 64 + 4);
            __half2 h0 = __floats2half2_rn(v0.x, v0.y);
            __half2 h1 = __floats2half2_rn(v0.z, v0.w);
            __half2 h2 = __floats2half2_rn(v1.x, v1.y);
            __half2 h3 = __floats2half2_rn(v1.z, v1.w);
            uint4 pk;
            pk.x = *reinterpret_cast<uint32_t*>(&h0);
            pk.y = *reinterpret_cast<uint32_t*>(&h1);
            pk.z = *reinterpret_cast<uint32_t*>(&h2);
            pk.w = *reinterpret_cast<uint32_t*>(&h3);
            *reinterpret_cast<uint4*>(
                reinterpret_cast<char*>(sm) + (a_dst - smbase) + s * IG_A_STAGE) = pk;
        }
        if (c + 1 < nch) {
            IG_LOAD_B(c + 1, s ^ 1);
            asm volatile("cp.async.wait_group 1;" ::: "memory");
        } else {
            asm volatile("cp.async.wait_group 0;" ::: "memory");
        }
        __syncthreads();

        const uint32_t aB = abase + (uint32_t)s * IG_A_STAGE + rowlow * 128;
        const uint32_t bB = smbase + (uint32_t)s * IG_B_STAGE +
                            ((uint32_t)wn0 + rowlow) * 128;
#pragma unroll
        for (int ks = 0; ks < 4; ks++) {
            const uint32_t ch = (((uint32_t)(ks << 1) + cbit) ^ xorv) << 4;
            uint32_t a[4], b[2][2];
            ldsm_x4(a[0], a[1], a[2], a[3], aB + ch);
            {
                uint32_t r0, r1, r2, r3;
                ldsm_x4(r0, r1, r2, r3, bB + ch);
                b[0][0] = r0;   // n 0-7,  k0-7
                b[1][0] = r1;   // n 8-15, k0-7
                b[0][1] = r2;   // n 0-7,  k8-15
                b[1][1] = r3;   // n 8-15, k8-15
            }
#pragma unroll
            for (int fn = 0; fn < 2; fn++) mma_f16(acc[fn], a, b[fn]);
        }
        __syncthreads();
    }
#undef IG_LOAD_B

    // epilogue: bias + fp32 store
#pragma unroll
    for (int fn = 0; fn < 2; fn++) {
        int cidx = n0 + wn0 + fn * 8 + 2 * tig;
        float bv0 = __ldg(bias + cidx);
        float bv1 = __ldg(bias + cidx + 1);
        float* r0p = C + (size_t)(m0 + gid) * DJ + cidx;
        float* r1p = C + (size_t)(m0 + gid + 8) * DJ + cidx;
        r0p[0] = acc[fn][0] + bv0;
        r0p[1] = acc[fn][1] + bv1;
        r1p[0] = acc[fn][2] + bv0;
        r1p[1] = acc[fn][3] + bv1;
    }
}

// ---------------------------------------------------------------------------
// Stage 2: Zh = fp16(tanh_hw(XT[bt,:] + YP[b*U+u,:]))
// Block per bt. Direct float4 loads (L1/L2-hot), 4 cols/thread, STG.64.
// ---------------------------------------------------------------------------
__global__ __launch_bounds__(256)
void z_tanh_kernel(const float* __restrict__ XT, const float* __restrict__ YP,
                   __half* __restrict__ Z) {
    const int bt = blockIdx.x;          // 0..1599
    const int b = bt / T_;
    const int tid = threadIdx.x;

    const int phase = tid >> 6;         // 0..3: u residue
    const int c4 = (tid & 63) * 4;      // column quad
    float4 xv = *(const float4*)(XT + (size_t)bt * DJ + c4);

    __half* zrow = Z + (size_t)bt * U_ * DJ + c4;
    const float* yb = YP + (size_t)b * U_ * DJ + c4;

#pragma unroll 5
    for (int u = phase; u < U_; u += 4) {
        float4 yv = *(const float4*)(yb + (size_t)u * DJ);
        __half2 h0 = __floats2half2_rn(fast_tanh(xv.x + yv.x), fast_tanh(xv.y + yv.y));
        __half2 h1 = __floats2half2_rn(fast_tanh(xv.z + yv.z), fast_tanh(xv.w + yv.w));
        uint2 pk;
        pk.x = *reinterpret_cast<uint32_t*>(&h0);
        pk.y = *reinterpret_cast<uint32_t*>(&h1);
        *reinterpret_cast<uint2*>(zrow + (size_t)u * DJ) = pk;
    }
}

// ---------------------------------------------------------------------------
// Stage 3: out = Zh @ Wh^T + b_cls, persistent CTAs (unchanged; pipe-bound).
// ---------------------------------------------------------------------------
#define BM 128
#define BN 128
#define BKH 64
#define ROWB 128
#define A_STAGE_BYTES (BM * ROWB)               // 16384
#define NSTAGES 3
#define B_BYTES (BN * DJ * 2)                   // 65536
#define B_OFF (NSTAGES * A_STAGE_BYTES)         // 49152
#define JSMEM (B_OFF + B_BYTES)                 // 114688
#define NCHUNKS (DJ / BKH)                      // 4
#define MGROUPS 37
#define MTILES (M_TOTAL / BM)                   // 1250
#define NJCTAS (8 * MGROUPS)                    // 296

__global__ __launch_bounds__(128, 2)
void joint_gemm_f16(const __half* __restrict__ Z, const __half* __restrict__ Wh,
                    const float* __restrict__ bias, float* __restrict__ out) {
    extern __shared__ char sm[];
    const uint32_t smbase = smem_u32(sm);
    const uint32_t bbase = smbase + B_OFF;

    const int K = DJ;
    const int N = V_;

    const int n0 = (blockIdx.x & 7) * BN;
    const int mgroup = blockIdx.x >> 3;
    const int tid = threadIdx.x;
    const int lane = tid & 31, w = tid >> 5;
    const int warpM = w & 1, warpN = w >> 1;
    const int wm0 = warpM * 64, wn0 = warpN * 64;
    const int gid = lane >> 2, tig = lane & 3;

    const int l8 = lane & 7, j = lane >> 3;
    const uint32_t rowlow = (uint32_t)(((j & 1) << 3) + l8);
    const uint32_t cbit = (uint32_t)(j >> 1);
    const uint32_t xorv = (uint32_t)l8;
    const uint32_t aRow = ((uint32_t)wm0 + rowlow) * ROWB;
    const uint32_t bRow = bbase + ((uint32_t)wn0 + rowlow) * 512;

    float bv[8][2];
#pragma unroll
    for (int fn = 0; fn < 8; fn++) {
        int cidx = n0 + wn0 + fn * 8 + 2 * tig;
        bv[fn][0] = bias[cidx];
        bv[fn][1] = bias[cidx + 1];
    }

    {
        int r = tid;
        const __half* src = Wh + (size_t)(n0 + r) * K;
        uint32_t dbase = bbase + (uint32_t)r * 512;
        uint32_t rx = (uint32_t)(r & 7);
#pragma unroll
        for (int ch = 0; ch < 32; ch++) {
            uint32_t d = dbase + (((uint32_t)ch ^ rx) << 4);
            asm volatile("cp.async.cg.shared.global [%0], [%1], 16;"
                         :: "r"(d), "l"(src + ch * 8));
        }
        asm volatile("cp.async.commit_group;" ::: "memory");
    }

    const int lrow = tid >> 3;
    const int lchunk = tid & 7;

#define LOAD_A(mt, c, s) do { \
    uint32_t _sb = smbase + (uint32_t)(s) * A_STAGE_BYTES; \
    _Pragma("unroll") \
    for (int p = 0; p < 8; p++) { \
        int _r = lrow + p * 16; \
        uint32_t _d = _sb + (uint32_t)_r * ROWB + \
                      ((uint32_t)(lchunk ^ (_r & 7)) << 4); \
        const __half* _a = Z + (size_t)((mt) * BM + _r) * K + (c) * BKH + lchunk * 8; \
        asm volatile("cp.async.cg.shared.global [%0], [%1], 16;" \
                     :: "r"(_d), "l"(_a)); \
    } \
    asm volatile("cp.async.commit_group;" ::: "memory"); \
} while (0)

    int lt = mgroup;
    int lc = 0;
    int ls = 0;
#define ADV_LOAD() do { \
    if (++lc == NCHUNKS) { lc = 0; lt += MGROUPS; if (lt >= MTILES) lt = -1; } \
    ls = (ls + 1 == NSTAGES) ? 0 : ls + 1; \
} while (0)

    LOAD_A(lt, lc, ls); ADV_LOAD();
    LOAD_A(lt, lc, ls); ADV_LOAD();

    int cs = 0;

#pragma unroll 1
    for (int t = mgroup; t < MTILES; t += MGROUPS) {
        const int m0 = t * BM;
        const bool lastTile = (t + MGROUPS >= MTILES);

        float acc[4][8][4];
#pragma unroll
        for (int fm = 0; fm < 4; fm++)
#pragma unroll
            for (int fn = 0; fn < 8; fn++)
#pragma unroll
                for (int r = 0; r < 4; r++) acc[fm][fn][r] = 0.f;

#pragma unroll
        for (int c = 0; c < NCHUNKS; c++) {
            if (lastTile && c == NCHUNKS - 1)
                asm volatile("cp.async.wait_group 0;" ::: "memory");
            else
                asm volatile("cp.async.wait_group 1;" ::: "memory");
            __syncthreads();
            if (lt >= 0) { LOAD_A(lt, lc, ls); ADV_LOAD(); }

            const uint32_t aB = smbase + (uint32_t)cs * A_STAGE_BYTES + aRow;
            cs = (cs + 1 == NSTAGES) ? 0 : cs + 1;
#pragma unroll
            for (int ks = 0; ks < 4; ks++) {
                const uint32_t aCh = (((uint32_t)(ks << 1) + cbit) ^ xorv) << 4;
                const uint32_t bCh = (((uint32_t)(c * 8 + (ks << 1)) + cbit) ^ xorv) << 4;
                uint32_t a[4][4], b[8][2];
#pragma unroll
                for (int fm = 0; fm < 4; fm++)
                    ldsm_x4(a[fm][0], a[fm][1], a[fm][2], a[fm][3],
                            aB + (uint32_t)fm * (16 * ROWB) + aCh);
#pragma unroll
                for (int p = 0; p < 4; p++) {
                    uint32_t r0, r1, r2, r3;
                    ldsm_x4(r0, r1, r2, r3, bRow + (uint32_t)p * (16 * 512) + bCh);
                    b[2 * p][0] = r0;
                    b[2 * p + 1][0] = r1;
                    b[2 * p][1] = r2;
                    b[2 * p + 1][1] = r3;
                }
#pragma unroll
                for (int fm = 0; fm < 4; fm++)
#pragma unroll
                    for (int fn = 0; fn < 8; fn++) mma_f16(acc[fm][fn], a[fm], b[fn]);
            }
        }

#pragma unroll
        for (int fm = 0; fm < 4; fm++) {
            int r0 = m0 + wm0 + fm * 16 + gid;
#pragma unroll
            for (int fn = 0; fn < 8; fn++) {
                int cidx = n0 + wn0 + fn * 8 + 2 * tig;
                float2 v0 = make_float2(acc[fm][fn][0] + bv[fn][0],
                                        acc[fm][fn][1] + bv[fn][1]);
                float2 v1 = make_float2(acc[fm][fn][2] + bv[fn][0],
                                        acc[fm][fn][3] + bv[fn][1]);
                *(float2*)(out + (size_t)r0 * N + cidx) = v0;
                *(float2*)(out + (size_t)(r0 + 8) * N + cidx) = v1;
            }
        }
    }
#undef LOAD_A
#undef ADV_LOAD
}

// ---------------------------------------------------------------------------
extern "C" void kernel_launch(void* const* d_in, const int* in_sizes, int n_in,
                              void* d_out, int out_size) {
    const float* x     = (const float*)d_in[0];
    const float* y     = (const float*)d_in[1];
    const float* W_tr  = (const float*)d_in[2];
    const float* b_tr  = (const float*)d_in[3];
    const float* W_pr  = (const float*)d_in[4];
    const float* b_pr  = (const float*)d_in[5];
    const float* W_cls = (const float*)d_in[6];
    const float* b_cls = (const float*)d_in[7];
    float* out = (float*)d_out;

    void *pXT, *pYP, *pZh, *pWh, *pWtrT, *pWprT;
    cudaGetSymbolAddress(&pXT, g_XT);
    cudaGetSymbolAddress(&pYP, g_YP);
    cudaGetSymbolAddress(&pZh, g_Zh);
    cudaGetSymbolAddress(&pWh, g_Wh);
    cudaGetSymbolAddress(&pWtrT, g_WtrT);
    cudaGetSymbolAddress(&pWprT, g_WprT);

    // weight preps
    {
        dim3 grid(V_ / 32, DJ / 32);
        transpose_w<<<grid, dim3(32, 8)>>>(W_cls, (__half*)pWh);
    }
    transpose_wk<<<dim3(DJ / 32, DTR / 32), dim3(32, 8)>>>(W_tr, (__half*)pWtrT, DTR);
    transpose_wk<<<dim3(DJ / 32, DPR / 32), dim3(32, 8)>>>(W_pr, (__half*)pWprT, DPR);

    // stage 1: XT and YP (fused, fp16 tensor, 500 small CTAs)
    {
        cudaFuncSetAttribute(in_gemm_f16, cudaFuncAttributeMaxDynamicSharedMemorySize,
                             IG_SMEM);
        in_gemm_f16<<<500, 128, IG_SMEM>>>(x, y, (const __half*)pWtrT,
                                           (const __half*)pWprT, b_tr, b_pr,
                                           (float*)pXT, (float*)pYP);
    }
    // stage 2
    z_tanh_kernel<<<B_ * T_, 256>>>((const float*)pXT, (const float*)pYP, (__half*)pZh);
    // stage 3 (persistent)
    {
        cudaFuncSetAttribute(joint_gemm_f16, cudaFuncAttributeMaxDynamicSharedMemorySize,
                             JSMEM);
        joint_gemm_f16<<<NJCTAS, 128, JSMEM>>>((const __half*)pZh, (const __half*)pWh,
                                               b_cls, out);
    }
}

// round 13
// speedup vs baseline: 2.8782x; 1.0045x over previous
#include <cuda_runtime.h>
#include <cuda_fp16.h>
#include <cstdint>

// ---------------------------------------------------------------------------
// RNN-T joint network (sm_103 legacy tensor path, fp16 mma everywhere):
//   XT = x@W_tr + b_tr   [1600,256] fp32 out, fp16 tensor math
//   YP = y@W_pr + b_pr   [400,256]  fp32 out, fp16 tensor math
//   Zh = fp16(tanh(XT[bt] + YP[b,u]))  [160000, 256]
//   out= Zh @ Wh + b_cls [160000,1024]  persistent fp16 mma (pipe-bound)
// Stage-1 v3: all-B-upfront cp.async prefetch (no per-chunk round trips).
// ---------------------------------------------------------------------------

#define B_  4
#define T_  400
#define U_  100
#define DTR 768
#define DPR 640
#define DJ  256
#define V_  1024
#define M_TOTAL (B_ * T_ * U_)   // 160000

__device__ float  g_XT[(size_t)B_ * T_ * DJ];
__device__ float  g_YP[(size_t)B_ * U_ * DJ];
__device__ __half g_Zh[(size_t)M_TOTAL * DJ];    // 82 MB
__device__ __half g_Wh[(size_t)V_ * DJ];         // fp16(W_cls^T)  [V][DJ]
__device__ __half g_WtrT[(size_t)DJ * DTR];      // fp16(W_tr^T)   [256][768]
__device__ __half g_WprT[(size_t)DJ * DPR];      // fp16(W_pr^T)   [256][640]

__device__ __forceinline__ float fast_tanh(float x) {
    float r;
    asm("tanh.approx.f32 %0, %1;" : "=f"(r) : "f"(x));
    return r;
}

__device__ __forceinline__ void mma_f16(float* c, const uint32_t* a, const uint32_t* b) {
    asm volatile(
        "mma.sync.aligned.m16n8k16.row.col.f32.f16.f16.f32 "
        "{%0,%1,%2,%3}, {%4,%5,%6,%7}, {%8,%9}, {%0,%1,%2,%3};\n"
        : "+f"(c[0]), "+f"(c[1]), "+f"(c[2]), "+f"(c[3])
        : "r"(a[0]), "r"(a[1]), "r"(a[2]), "r"(a[3]), "r"(b[0]), "r"(b[1]));
}

__device__ __forceinline__ void ldsm_x4(uint32_t& r0, uint32_t& r1, uint32_t& r2,
                                        uint32_t& r3, uint32_t addr) {
    asm volatile("ldmatrix.sync.aligned.m8n8.x4.shared.b16 {%0,%1,%2,%3}, [%4];"
                 : "=r"(r0), "=r"(r1), "=r"(r2), "=r"(r3) : "r"(addr));
}

__device__ __forceinline__ void ldsm_x2(uint32_t& r0, uint32_t& r1, uint32_t addr) {
    asm volatile("ldmatrix.sync.aligned.m8n8.x2.shared.b16 {%0,%1}, [%2];"
                 : "=r"(r0), "=r"(r1) : "r"(addr));
}

__device__ __forceinline__ uint32_t smem_u32(const void* p) {
    uint32_t a;
    asm("{ .reg .u64 t; cvta.to.shared.u64 t, %1; cvt.u32.u64 %0, t; }" : "=r"(a) : "l"(p));
    return a;
}

// ---------------------------------------------------------------------------
// Stage 0 (merged): all three weight transposes+fp16 in one launch.
//   idx   0..255 : Wh  [n<V_][k<DJ]  from W_cls[k*V_+n]
//   idx 256..447 : WtrT[n<DJ][k<DTR] from W_tr [k*DJ+n]
//   idx 448..607 : WprT[n<DJ][k<DPR] from W_pr [k*DJ+n]
// ---------------------------------------------------------------------------
__global__ __launch_bounds__(256)
void prep_weights(const float* __restrict__ Wcls, const float* __restrict__ Wtr,
                  const float* __restrict__ Wpr, __half* __restrict__ Wh,
                  __half* __restrict__ WtrT, __half* __restrict__ WprT) {
    __shared__ float t[32][33];
    const int idx = blockIdx.x;
    const float* W;
    __half* D;
    int srcN, dstK, n0, k0;
    if (idx < 256) {
        W = Wcls; D = Wh; srcN = V_; dstK = DJ;
        n0 = (idx & 31) * 32; k0 = (idx >> 5) * 32;
    } else if (idx < 448) {
        int i = idx - 256;
        W = Wtr; D = WtrT; srcN = DJ; dstK = DTR;
        n0 = (i & 7) * 32; k0 = (i >> 3) * 32;
    } else {
        int i = idx - 448;
        W = Wpr; D = WprT; srcN = DJ; dstK = DPR;
        n0 = (i & 7) * 32; k0 = (i >> 3) * 32;
    }
    int tx = threadIdx.x, ty = threadIdx.y;   // (32, 8)
#pragma unroll
    for (int i = 0; i < 32; i += 8)
        t[ty + i][tx] = W[(size_t)(k0 + ty + i) * srcN + n0 + tx];
    __syncthreads();
#pragma unroll
    for (int i = 0; i < 32; i += 8)
        D[(size_t)(n0 + ty + i) * dstK + k0 + tx] = __float2half_rn(t[tx][ty + i]);
}

// ---------------------------------------------------------------------------
// Stage 1 v3 (fused XT + YP): fp16 tensor GEMM, fp32-out, all-B prefetched.
// Tile 16m x 32n, 128 threads (4 warps x 8n). Grid 1000:
//   blk 0..799:   XT  mt = blk>>3, n-slice = blk&7  (K = 768, 12 chunks)
//   blk 800..999: YP  (K = 640, 10 chunks)
// Smem: B 12 chunks x [32n][128B] = 48KB (no reuse), A 12 x [16m][128B] = 24KB.
// Prologue: ALL B cp.async groups issued (padded to 12 commits so the
// per-chunk wait_group count is a compile-time constant), A converted
// fp32->fp16 with high MLP. Main loop has NO loads -- wait+sync+ldsm+mma.
// Accumulation order (c, ks) identical to v2 -> bitwise-identical outputs.
// ---------------------------------------------------------------------------
#define IG_B_CH 4096                        // 32 * 128
#define IG_A_CH 2048                        // 16 * 128
#define IG_MAXCH 12
#define IG_SMEM (IG_MAXCH * (IG_B_CH + IG_A_CH))   // 73728

__global__ __launch_bounds__(128)
void in_gemm_f16(const float* __restrict__ x, const float* __restrict__ y,
                 const __half* __restrict__ WtrT, const __half* __restrict__ WprT,
                 const float* __restrict__ btr, const float* __restrict__ bpr,
                 float* __restrict__ XT, float* __restrict__ YP) {
    extern __shared__ char sm[];
    const uint32_t smbase = smem_u32(sm);
    const uint32_t abase = smbase + IG_MAXCH * IG_B_CH;

    const int blk = blockIdx.x;
    const bool isY = blk >= 800;
    const int bidx = isY ? blk - 800 : blk;
    const float* A = isY ? y : x;
    const __half* Wt = isY ? WprT : WtrT;
    const float* bias = isY ? bpr : btr;
    float* C = isY ? YP : XT;
    const int m0 = (bidx >> 3) * 16;
    const int n0 = (bidx & 7) * 32;
    const int K = isY ? DPR : DTR;
    const int nch = K / 64;                  // 12 or 10

    const int tid = threadIdx.x;
    const int lane = tid & 31, w = tid >> 5;
    const int gid = lane >> 2, tig = lane & 3;

    // ---- B prefetch: thread t -> row t>>2, chunks (t&3)*2 and +1 ----
    {
        const int b_row = tid >> 2;
        const int b_c0 = (tid & 3) * 2;
        const __half* b_src = Wt + (size_t)(n0 + b_row) * K;
        const uint32_t b_dst = smbase + (uint32_t)b_row * 128;
        const uint32_t brx = (uint32_t)(b_row & 7);
#pragma unroll 4
        for (int c = 0; c < nch; c++) {
#pragma unroll
            for (int i = 0; i < 2; i++) {
                uint32_t ch = (uint32_t)(b_c0 + i);
                asm volatile("cp.async.cg.shared.global [%0], [%1], 16;"
                             :: "r"(b_dst + (uint32_t)c * IG_B_CH + ((ch ^ brx) << 4)),
                                "l"(b_src + c * 64 + ch * 8));
            }
            asm volatile("cp.async.commit_group;" ::: "memory");
        }
        for (int c = nch; c < IG_MAXCH; c++)
            asm volatile("cp.async.commit_group;" ::: "memory");   // empty groups
    }

    // ---- A convert: thread t -> row t>>3, 16B chunk t&7, all nch chunks ----
    {
        const int a_row = tid >> 3;
        const int a_ch = tid & 7;
        const float* a_srcp = A + (size_t)(m0 + a_row) * K + a_ch * 8;
        char* a_dstp = sm + (IG_MAXCH * IG_B_CH) + a_row * 128 +
                       (((uint32_t)a_ch ^ (uint32_t)(a_row & 7)) << 4);
#pragma unroll 4
        for (int c = 0; c < nch; c++) {
            float4 v0 = *(const float4*)(a_srcp + c * 64);
            float4 v1 = *(const float4*)(a_srcp + c * 64 + 4);
            __half2 h0 = __floats2half2_rn(v0.x, v0.y);
            __half2 h1 = __floats2half2_rn(v0.z, v0.w);
            __half2 h2 = __floats2half2_rn(v1.x, v1.y);
            __half2 h3 = __floats2half2_rn(v1.z, v1.w);
            uint4 pk;
            pk.x = *reinterpret_cast<uint32_t*>(&h0);
            pk.y = *reinterpret_cast<uint32_t*>(&h1);
            pk.z = *reinterpret_cast<uint32_t*>(&h2);
            pk.w = *reinterpret_cast<uint32_t*>(&h3);
            *reinterpret_cast<uint4*>(a_dstp + c * IG_A_CH) = pk;
        }
    }

    // ---- fragment lane mappings ----
    // A (x4): as verified in joint kernel
    const int l8 = lane & 7, j = lane >> 3;
    const uint32_t rowlowA = (uint32_t)(((j & 1) << 3) + l8);
    const uint32_t cbitA = (uint32_t)(j >> 1);
    const uint32_t xorvA = (uint32_t)l8;
    const uint32_t aBase = abase + rowlowA * 128;
    // B (x2): lanes 0-15 -> matrix jb = l16>>3 (k-halves), row = l16&7
    const int l16 = lane & 15;
    const uint32_t jb = (uint32_t)(l16 >> 3);
    const uint32_t rowB = (uint32_t)(w * 8 + (l16 & 7));
    const uint32_t xorvB = (uint32_t)(l16 & 7);
    const uint32_t bBase = smbase + rowB * 128;

    float acc[4];
    acc[0] = acc[1] = acc[2] = acc[3] = 0.f;

#define IG_CHUNK(c) \
    if ((c) < nch) { \
        asm volatile("cp.async.wait_group %0;" :: "n"(IG_MAXCH - 1 - (c)) : "memory"); \
        __syncthreads(); \
        _Pragma("unroll") \
        for (int ks = 0; ks < 4; ks++) { \
            uint32_t a[4], b[2]; \
            ldsm_x4(a[0], a[1], a[2], a[3], \
                    aBase + (c) * IG_A_CH + \
                    ((((uint32_t)(ks << 1) + cbitA) ^ xorvA) << 4)); \
            ldsm_x2(b[0], b[1], \
                    bBase + (c) * IG_B_CH + \
                    ((((uint32_t)(ks << 1) + jb) ^ xorvB) << 4)); \
            mma_f16(acc, a, b); \
        } \
    }

    IG_CHUNK(0);  IG_CHUNK(1);  IG_CHUNK(2);  IG_CHUNK(3);
    IG_CHUNK(4);  IG_CHUNK(5);  IG_CHUNK(6);  IG_CHUNK(7);
    IG_CHUNK(8);  IG_CHUNK(9);  IG_CHUNK(10); IG_CHUNK(11);
#undef IG_CHUNK

    // epilogue: bias + fp32 store (warp w owns n [w*8, w*8+8))
    {
        int cidx = n0 + w * 8 + 2 * tig;
        float bv0 = __ldg(bias + cidx);
        float bv1 = __ldg(bias + cidx + 1);
        float* r0p = C + (size_t)(m0 + gid) * DJ + cidx;
        float* r1p = C + (size_t)(m0 + gid + 8) * DJ + cidx;
        r0p[0] = acc[0] + bv0;
        r0p[1] = acc[1] + bv1;
        r1p[0] = acc[2] + bv0;
        r1p[1] = acc[3] + bv1;
    }
}

// ---------------------------------------------------------------------------
// Stage 2: Zh = fp16(tanh_hw(XT[bt,:] + YP[b*U+u,:]))
// ---------------------------------------------------------------------------
__global__ __launch_bounds__(256)
void z_tanh_kernel(const float* __restrict__ XT, const float* __restrict__ YP,
                   __half* __restrict__ Z) {
    const int bt = blockIdx.x;          // 0..1599
    const int b = bt / T_;
    const int tid = threadIdx.x;

    const int phase = tid >> 6;         // 0..3: u residue
    const int c4 = (tid & 63) * 4;      // column quad
    float4 xv = *(const float4*)(XT + (size_t)bt * DJ + c4);

    __half* zrow = Z + (size_t)bt * U_ * DJ + c4;
    const float* yb = YP + (size_t)b * U_ * DJ + c4;

#pragma unroll 5
    for (int u = phase; u < U_; u += 4) {
        float4 yv = *(const float4*)(yb + (size_t)u * DJ);
        __half2 h0 = __floats2half2_rn(fast_tanh(xv.x + yv.x), fast_tanh(xv.y + yv.y));
        __half2 h1 = __floats2half2_rn(fast_tanh(xv.z + yv.z), fast_tanh(xv.w + yv.w));
        uint2 pk;
        pk.x = *reinterpret_cast<uint32_t*>(&h0);
        pk.y = *reinterpret_cast<uint32_t*>(&h1);
        *reinterpret_cast<uint2*>(zrow + (size_t)u * DJ) = pk;
    }
}

// ---------------------------------------------------------------------------
// Stage 3: out = Zh @ Wh^T + b_cls, persistent CTAs (pipe-bound; unchanged).
// ---------------------------------------------------------------------------
#define BM 128
#define BN 128
#define BKH 64
#define ROWB 128
#define A_STAGE_BYTES (BM * ROWB)               // 16384
#define NSTAGES 3
#define B_BYTES (BN * DJ * 2)                   // 65536
#define B_OFF (NSTAGES * A_STAGE_BYTES)         // 49152
#define JSMEM (B_OFF + B_BYTES)                 // 114688
#define NCHUNKS (DJ / BKH)                      // 4
#define MGROUPS 37
#define MTILES (M_TOTAL / BM)                   // 1250
#define NJCTAS (8 * MGROUPS)                    // 296

__global__ __launch_bounds__(128, 2)
void joint_gemm_f16(const __half* __restrict__ Z, const __half* __restrict__ Wh,
                    const float* __restrict__ bias, float* __restrict__ out) {
    extern __shared__ char sm[];
    const uint32_t smbase = smem_u32(sm);
    const uint32_t bbase = smbase + B_OFF;

    const int K = DJ;
    const int N = V_;

    const int n0 = (blockIdx.x & 7) * BN;
    const int mgroup = blockIdx.x >> 3;
    const int tid = threadIdx.x;
    const int lane = tid & 31, w = tid >> 5;
    const int warpM = w & 1, warpN = w >> 1;
    const int wm0 = warpM * 64, wn0 = warpN * 64;
    const int gid = lane >> 2, tig = lane & 3;

    const int l8 = lane & 7, j = lane >> 3;
    const uint32_t rowlow = (uint32_t)(((j & 1) << 3) + l8);
    const uint32_t cbit = (uint32_t)(j >> 1);
    const uint32_t xorv = (uint32_t)l8;
    const uint32_t aRow = ((uint32_t)wm0 + rowlow) * ROWB;
    const uint32_t bRow = bbase + ((uint32_t)wn0 + rowlow) * 512;

    float bv[8][2];
#pragma unroll
    for (int fn = 0; fn < 8; fn++) {
        int cidx = n0 + wn0 + fn * 8 + 2 * tig;
        bv[fn][0] = bias[cidx];
        bv[fn][1] = bias[cidx + 1];
    }

    {
        int r = tid;
        const __half* src = Wh + (size_t)(n0 + r) * K;
        uint32_t dbase = bbase + (uint32_t)r * 512;
        uint32_t rx = (uint32_t)(r & 7);
#pragma unroll
        for (int ch = 0; ch < 32; ch++) {
            uint32_t d = dbase + (((uint32_t)ch ^ rx) << 4);
            asm volatile("cp.async.cg.shared.global [%0], [%1], 16;"
                         :: "r"(d), "l"(src + ch * 8));
        }
        asm volatile("cp.async.commit_group;" ::: "memory");
    }

    const int lrow = tid >> 3;
    const int lchunk = tid & 7;

#define LOAD_A(mt, c, s) do { \
    uint32_t _sb = smbase + (uint32_t)(s) * A_STAGE_BYTES; \
    _Pragma("unroll") \
    for (int p = 0; p < 8; p++) { \
        int _r = lrow + p * 16; \
        uint32_t _d = _sb + (uint32_t)_r * ROWB + \
                      ((uint32_t)(lchunk ^ (_r & 7)) << 4); \
        const __half* _a = Z + (size_t)((mt) * BM + _r) * K + (c) * BKH + lchunk * 8; \
        asm volatile("cp.async.cg.shared.global [%0], [%1], 16;" \
                     :: "r"(_d), "l"(_a)); \
    } \
    asm volatile("cp.async.commit_group;" ::: "memory"); \
} while (0)

    int lt = mgroup;
    int lc = 0;
    int ls = 0;
#define ADV_LOAD() do { \
    if (++lc == NCHUNKS) { lc = 0; lt += MGROUPS; if (lt >= MTILES) lt = -1; } \
    ls = (ls + 1 == NSTAGES) ? 0 : ls + 1; \
} while (0)

    LOAD_A(lt, lc, ls); ADV_LOAD();
    LOAD_A(lt, lc, ls); ADV_LOAD();

    int cs = 0;

#pragma unroll 1
    for (int t = mgroup; t < MTILES; t += MGROUPS) {
        const int m0 = t * BM;
        const bool lastTile = (t + MGROUPS >= MTILES);

        float acc[4][8][4];
#pragma unroll
        for (int fm = 0; fm < 4; fm++)
#pragma unroll
            for (int fn = 0; fn < 8; fn++)
#pragma unroll
                for (int r = 0; r < 4; r++) acc[fm][fn][r] = 0.f;

#pragma unroll
        for (int c = 0; c < NCHUNKS; c++) {
            if (lastTile && c == NCHUNKS - 1)
                asm volatile("cp.async.wait_group 0;" ::: "memory");
            else
                asm volatile("cp.async.wait_group 1;" ::: "memory");
            __syncthreads();
            if (lt >= 0) { LOAD_A(lt, lc, ls); ADV_LOAD(); }

            const uint32_t aB = smbase + (uint32_t)cs * A_STAGE_BYTES + aRow;
            cs = (cs + 1 == NSTAGES) ? 0 : cs + 1;
#pragma unroll
            for (int ks = 0; ks < 4; ks++) {
                const uint32_t aCh = (((uint32_t)(ks << 1) + cbit) ^ xorv) << 4;
                const uint32_t bCh = (((uint32_t)(c * 8 + (ks << 1)) + cbit) ^ xorv) << 4;
                uint32_t a[4][4], b[8][2];
#pragma unroll
                for (int fm = 0; fm < 4; fm++)
                    ldsm_x4(a[fm][0], a[fm][1], a[fm][2], a[fm][3],
                            aB + (uint32_t)fm * (16 * ROWB) + aCh);
#pragma unroll
                for (int p = 0; p < 4; p++) {
                    uint32_t r0, r1, r2, r3;
                    ldsm_x4(r0, r1, r2, r3, bRow + (uint32_t)p * (16 * 512) + bCh);
                    b[2 * p][0] = r0;
                    b[2 * p + 1][0] = r1;
                    b[2 * p][1] = r2;
                    b[2 * p + 1][1] = r3;
                }
#pragma unroll
                for (int fm = 0; fm < 4; fm++)
#pragma unroll
                    for (int fn = 0; fn < 8; fn++) mma_f16(acc[fm][fn], a[fm], b[fn]);
            }
        }

#pragma unroll
        for (int fm = 0; fm < 4; fm++) {
            int r0 = m0 + wm0 + fm * 16 + gid;
#pragma unroll
            for (int fn = 0; fn < 8; fn++) {
                int cidx = n0 + wn0 + fn * 8 + 2 * tig;
                float2 v0 = make_float2(acc[fm][fn][0] + bv[fn][0],
                                        acc[fm][fn][1] + bv[fn][1]);
                float2 v1 = make_float2(acc[fm][fn][2] + bv[fn][0],
                                        acc[fm][fn][3] + bv[fn][1]);
                *(float2*)(out + (size_t)r0 * N + cidx) = v0;
                *(float2*)(out + (size_t)(r0 + 8) * N + cidx) = v1;
            }
        }
    }
#undef LOAD_A
#undef ADV_LOAD
}

// ---------------------------------------------------------------------------
extern "C" void kernel_launch(void* const* d_in, const int* in_sizes, int n_in,
                              void* d_out, int out_size) {
    const float* x     = (const float*)d_in[0];
    const float* y     = (const float*)d_in[1];
    const float* W_tr  = (const float*)d_in[2];
    const float* b_tr  = (const float*)d_in[3];
    const float* W_pr  = (const float*)d_in[4];
    const float* b_pr  = (const float*)d_in[5];
    const float* W_cls = (const float*)d_in[6];
    const float* b_cls = (const float*)d_in[7];
    float* out = (float*)d_out;

    void *pXT, *pYP, *pZh, *pWh, *pWtrT, *pWprT;
    cudaGetSymbolAddress(&pXT, g_XT);
    cudaGetSymbolAddress(&pYP, g_YP);
    cudaGetSymbolAddress(&pZh, g_Zh);
    cudaGetSymbolAddress(&pWh, g_Wh);
    cudaGetSymbolAddress(&pWtrT, g_WtrT);
    cudaGetSymbolAddress(&pWprT, g_WprT);

    // stage 0: all weight preps in one launch
    prep_weights<<<608, dim3(32, 8)>>>(W_cls, W_tr, W_pr, (__half*)pWh,
                                       (__half*)pWtrT, (__half*)pWprT);

    // stage 1: XT and YP (fused, fp16 tensor, all-B prefetch)
    {
        cudaFuncSetAttribute(in_gemm_f16, cudaFuncAttributeMaxDynamicSharedMemorySize,
                             IG_SMEM);
        in_gemm_f16<<<1000, 128, IG_SMEM>>>(x, y, (const __half*)pWtrT,
                                            (const __half*)pWprT, b_tr, b_pr,
                                            (float*)pXT, (float*)pYP);
    }
    // stage 2
    z_tanh_kernel<<<B_ * T_, 256>>>((const float*)pXT, (const float*)pYP, (__half*)pZh);
    // stage 3 (persistent)
    {
        cudaFuncSetAttribute(joint_gemm_f16, cudaFuncAttributeMaxDynamicSharedMemorySize,
                             JSMEM);
        joint_gemm_f16<<<NJCTAS, 128, JSMEM>>>((const __half*)pZh, (const __half*)pWh,
                                               b_cls, out);
    }
}